// round 1
// baseline (speedup 1.0000x reference)
#include <cuda_runtime.h>
#include <math.h>

// Problem dimensions (fixed by the dataset)
#define B_  2
#define S_  2048
#define D_  2048
#define QH_ 16
#define KH_ 4
#define HD_ 128
#define M_ROWS (B_ * S_)   // 4096

// ---------------------------------------------------------------------------
// Scratch (no allocations allowed -> __device__ globals)
// ---------------------------------------------------------------------------
__device__ float g_q[B_ * S_ * QH_ * HD_];   // 8M floats
__device__ float g_k[B_ * S_ * KH_ * HD_];   // 2M
__device__ float g_v[B_ * S_ * KH_ * HD_];   // 2M
__device__ float g_att[B_ * S_ * QH_ * HD_]; // 8M

// ---------------------------------------------------------------------------
// SGEMM: C[M,N] = A[M,K] @ W
//   HEADB=true : W is [n_heads, K, 128]; N-block bcol/128 selects the head,
//                within a head W is plain row-major [K,128].
//   HEADB=false: W is plain row-major [K,N].
// 128x128 block tile, 8-deep K slice, 8x8 register tile, 256 threads.
// ---------------------------------------------------------------------------
template <bool HEADB>
__global__ __launch_bounds__(256) void sgemm128(const float* __restrict__ A,
                                                const float* __restrict__ W,
                                                float* __restrict__ C,
                                                int M, int N, int K) {
    __shared__ float As[8][128];
    __shared__ float Bs[8][128];

    const int tid  = threadIdx.x;
    const int brow = blockIdx.y * 128;
    const int bcol = blockIdx.x * 128;

    const int a_row = tid >> 1;           // 0..127
    const int a_col = (tid & 1) << 2;     // 0 or 4
    const int b_row = tid >> 5;           // 0..7
    const int b_col = (tid & 31) << 2;    // 0..124

    const int tx = tid & 15;
    const int ty = tid >> 4;

    const float* Aptr = A + (size_t)(brow + a_row) * K + a_col;
    const float* Bptr;
    size_t b_kstride;
    if (HEADB) {
        // head = bcol / 128 == blockIdx.x
        Bptr = W + (size_t)blockIdx.x * K * 128 + (size_t)b_row * 128 + b_col;
        b_kstride = 128;
    } else {
        Bptr = W + (size_t)b_row * N + bcol + b_col;
        b_kstride = N;
    }

    float acc[8][8];
#pragma unroll
    for (int i = 0; i < 8; i++)
#pragma unroll
        for (int j = 0; j < 8; j++) acc[i][j] = 0.f;

    for (int k0 = 0; k0 < K; k0 += 8) {
        float4 av = *(const float4*)(Aptr + k0);
        float4 bv = *(const float4*)(Bptr + (size_t)k0 * b_kstride);
        As[a_col + 0][a_row] = av.x;
        As[a_col + 1][a_row] = av.y;
        As[a_col + 2][a_row] = av.z;
        As[a_col + 3][a_row] = av.w;
        *(float4*)&Bs[b_row][b_col] = bv;
        __syncthreads();

#pragma unroll
        for (int kk = 0; kk < 8; kk++) {
            float af[8], bf[8];
            float4 a0 = *(const float4*)&As[kk][ty * 8];
            float4 a1 = *(const float4*)&As[kk][ty * 8 + 4];
            float4 b0 = *(const float4*)&Bs[kk][tx * 8];
            float4 b1 = *(const float4*)&Bs[kk][tx * 8 + 4];
            af[0]=a0.x; af[1]=a0.y; af[2]=a0.z; af[3]=a0.w;
            af[4]=a1.x; af[5]=a1.y; af[6]=a1.z; af[7]=a1.w;
            bf[0]=b0.x; bf[1]=b0.y; bf[2]=b0.z; bf[3]=b0.w;
            bf[4]=b1.x; bf[5]=b1.y; bf[6]=b1.z; bf[7]=b1.w;
#pragma unroll
            for (int i = 0; i < 8; i++)
#pragma unroll
                for (int j = 0; j < 8; j++) acc[i][j] = fmaf(af[i], bf[j], acc[i][j]);
        }
        __syncthreads();
    }

#pragma unroll
    for (int i = 0; i < 8; i++) {
        size_t row = (size_t)brow + ty * 8 + i;
        float* cp = C + row * N + bcol + tx * 8;
        float4 c0 = make_float4(acc[i][0], acc[i][1], acc[i][2], acc[i][3]);
        float4 c1 = make_float4(acc[i][4], acc[i][5], acc[i][6], acc[i][7]);
        *(float4*)cp = c0;
        *(float4*)(cp + 4) = c1;
    }
}

// ---------------------------------------------------------------------------
// RoPE (in-place) on [B, S, NH, 128]
// ---------------------------------------------------------------------------
__global__ void rope_kernel(float* __restrict__ x, const int* __restrict__ positions,
                            int NH, int total) {
    int i = blockIdx.x * blockDim.x + threadIdx.x;
    if (i >= total) return;
    int hp = i & 63;            // 0..63 (half dim)
    int rest = i >> 6;
    int nh = rest % NH;
    int s  = (rest / NH) % S_;
    int b  = rest / (NH * S_);

    float pos = (float)positions[s];
    // timescale = 10000 ^ (hp/64), computed in fp32 like the reference
    float ts  = expf(((float)hp / 64.f) * 9.21034037197618f /* ln(1e4) */);
    float ang = pos / ts;
    float sn = sinf(ang);
    float cs = cosf(ang);

    size_t base = ((size_t)(b * S_ + s) * NH + nh) * HD_;
    float x1 = x[base + hp];
    float x2 = x[base + hp + 64];
    x[base + hp]      = x1 * cs - x2 * sn;
    x[base + hp + 64] = x2 * cs + x1 * sn;
}

// ---------------------------------------------------------------------------
// Flash attention (causal, GQA).  Grid: (S/64 query tiles, B*QH).
// Q,K kept transposed in smem ([h][row]) so the 64x64 score GEMM reads
// conflict-free float4s and the per-row softmax scan is a contiguous column.
// ---------------------------------------------------------------------------
#define FBM 64
#define FBN 64
#define QS 68   // FBM + 4 pad
#define KS 68
#define VS 132  // HD_ + 4 pad
#define PS 68

#define FLASH_SMEM ((HD_ * QS + HD_ * KS + FBN * VS + FBN * PS + 3 * FBM) * 4)

__global__ __launch_bounds__(256) void flash_kernel(const float* __restrict__ Q,
                                                    const float* __restrict__ K,
                                                    const float* __restrict__ V,
                                                    float* __restrict__ O) {
    extern __shared__ float sm[];
    float* Qst = sm;                    // [128][QS]
    float* Kst = Qst + HD_ * QS;        // [128][KS]
    float* Vs  = Kst + HD_ * KS;        // [64][VS]
    float* Pst = Vs + FBN * VS;         // [64][PS]  (P transposed: [j][i])
    float* rm  = Pst + FBN * PS;        // [64]
    float* rl  = rm + FBM;              // [64]
    float* rc  = rl + FBM;              // [64]

    const int tid = threadIdx.x;
    const int mblk = gridDim.x - 1 - blockIdx.x;   // heavy tiles first
    const int bq = blockIdx.y;
    const int b  = bq / QH_;
    const int qh = bq % QH_;
    const int kvh = qh / (QH_ / KH_);

    // Load Q tile, transposed into smem
    for (int idx = tid; idx < FBM * (HD_ / 4); idx += 256) {
        int r  = idx >> 5;
        int c4 = idx & 31;
        int s  = mblk * FBM + r;
        float4 v4 = *(const float4*)(Q + ((size_t)(b * S_ + s) * QH_ + qh) * HD_ + c4 * 4);
        int h = c4 * 4;
        Qst[(h + 0) * QS + r] = v4.x;
        Qst[(h + 1) * QS + r] = v4.y;
        Qst[(h + 2) * QS + r] = v4.z;
        Qst[(h + 3) * QS + r] = v4.w;
    }
    if (tid < FBM) { rm[tid] = -INFINITY; rl[tid] = 0.f; }

    const int ty = tid >> 4;   // 0..15
    const int tx = tid & 15;   // 0..15
    const int i0 = ty * 4;     // query row group
    const int j0 = tx * 4;     // score col group
    const int h0 = tx * 8;     // output dim group

    float oacc[4][8];
#pragma unroll
    for (int i = 0; i < 4; i++)
#pragma unroll
        for (int j = 0; j < 8; j++) oacc[i][j] = 0.f;

    const float scale = 0.08838834764831845f;  // 1/sqrt(128)

    for (int n = 0; n <= mblk; n++) {
        __syncthreads();  // protect Kst/Vs/Pst reuse (also covers Q-load for n==0)

        // Load K tile transposed, V tile direct
        for (int idx = tid; idx < FBN * (HD_ / 4); idx += 256) {
            int r  = idx >> 5;
            int c4 = idx & 31;
            int t  = n * FBN + r;
            size_t gbase = ((size_t)(b * S_ + t) * KH_ + kvh) * HD_ + c4 * 4;
            float4 kv = *(const float4*)(K + gbase);
            int h = c4 * 4;
            Kst[(h + 0) * KS + r] = kv.x;
            Kst[(h + 1) * KS + r] = kv.y;
            Kst[(h + 2) * KS + r] = kv.z;
            Kst[(h + 3) * KS + r] = kv.w;
            float4 vv = *(const float4*)(V + gbase);
            *(float4*)&Vs[r * VS + c4 * 4] = vv;
        }
        __syncthreads();

        // Scores: 4x4 per thread over h=0..127
        float sa[4][4];
#pragma unroll
        for (int i = 0; i < 4; i++)
#pragma unroll
            for (int j = 0; j < 4; j++) sa[i][j] = 0.f;

#pragma unroll 8
        for (int h = 0; h < HD_; h++) {
            float4 a = *(const float4*)&Qst[h * QS + i0];
            float4 bb = *(const float4*)&Kst[h * KS + j0];
            float af[4] = {a.x, a.y, a.z, a.w};
            float bf[4] = {bb.x, bb.y, bb.z, bb.w};
#pragma unroll
            for (int i = 0; i < 4; i++)
#pragma unroll
                for (int j = 0; j < 4; j++) sa[i][j] = fmaf(af[i], bf[j], sa[i][j]);
        }

        const int gi0 = mblk * FBM + i0;
        const int gj0 = n * FBN + j0;
#pragma unroll
        for (int j = 0; j < 4; j++)
#pragma unroll
            for (int i = 0; i < 4; i++) {
                float vx = sa[i][j] * scale;
                if (gj0 + j > gi0 + i) vx = -1e9f;
                Pst[(j0 + j) * PS + (i0 + i)] = vx;
            }
        __syncthreads();

        // Online softmax: one thread per query row (column scan of Pst)
        if (tid < FBM) {
            int i = tid;
            float mo = rm[i];
            float mx = mo;
#pragma unroll 8
            for (int j = 0; j < FBN; j++) mx = fmaxf(mx, Pst[j * PS + i]);
            float corr = __expf(mo - mx);
            float l = rl[i] * corr;
#pragma unroll 8
            for (int j = 0; j < FBN; j++) {
                float p = __expf(Pst[j * PS + i] - mx);
                Pst[j * PS + i] = p;
                l += p;
            }
            rm[i] = mx;
            rl[i] = l;
            rc[i] = corr;
        }
        __syncthreads();

        // Rescale O and accumulate P @ V  (4 rows x 8 dims per thread)
        float cr[4] = {rc[i0], rc[i0 + 1], rc[i0 + 2], rc[i0 + 3]};
#pragma unroll
        for (int i = 0; i < 4; i++)
#pragma unroll
            for (int j = 0; j < 8; j++) oacc[i][j] *= cr[i];

#pragma unroll 4
        for (int j = 0; j < FBN; j++) {
            float4 p4 = *(const float4*)&Pst[j * PS + i0];
            float4 v0 = *(const float4*)&Vs[j * VS + h0];
            float4 v1 = *(const float4*)&Vs[j * VS + h0 + 4];
            float pf[4] = {p4.x, p4.y, p4.z, p4.w};
            float vf[8] = {v0.x, v0.y, v0.z, v0.w, v1.x, v1.y, v1.z, v1.w};
#pragma unroll
            for (int i = 0; i < 4; i++)
#pragma unroll
                for (int hh = 0; hh < 8; hh++) oacc[i][hh] = fmaf(pf[i], vf[hh], oacc[i][hh]);
        }
    }

    // Epilogue: divide by row sum, write out [B,S,QH,H]
#pragma unroll
    for (int i = 0; i < 4; i++) {
        float inv = 1.0f / rl[i0 + i];
        int s = mblk * FBM + i0 + i;
        float* op = O + ((size_t)(b * S_ + s) * QH_ + qh) * HD_ + h0;
        float4 o0 = make_float4(oacc[i][0] * inv, oacc[i][1] * inv,
                                oacc[i][2] * inv, oacc[i][3] * inv);
        float4 o1 = make_float4(oacc[i][4] * inv, oacc[i][5] * inv,
                                oacc[i][6] * inv, oacc[i][7] * inv);
        *(float4*)op = o0;
        *(float4*)(op + 4) = o1;
    }
}

// ---------------------------------------------------------------------------
// Launch
// ---------------------------------------------------------------------------
extern "C" void kernel_launch(void* const* d_in, const int* in_sizes, int n_in,
                              void* d_out, int out_size) {
    const float* x         = (const float*)d_in[0];
    const int*   positions = (const int*)d_in[1];
    const float* Wq        = (const float*)d_in[2];
    const float* Wk        = (const float*)d_in[3];
    const float* Wv        = (const float*)d_in[4];
    const float* Wo        = (const float*)d_in[5];
    float* out = (float*)d_out;

    float *q, *k, *v, *att;
    cudaGetSymbolAddress((void**)&q,   g_q);
    cudaGetSymbolAddress((void**)&k,   g_k);
    cudaGetSymbolAddress((void**)&v,   g_v);
    cudaGetSymbolAddress((void**)&att, g_att);

    // Projections: q = x @ Wq (head-blocked), k/v likewise
    sgemm128<true><<<dim3(QH_, M_ROWS / 128), 256>>>(x, Wq, q, M_ROWS, QH_ * HD_, D_);
    sgemm128<true><<<dim3(KH_, M_ROWS / 128), 256>>>(x, Wk, k, M_ROWS, KH_ * HD_, D_);
    sgemm128<true><<<dim3(KH_, M_ROWS / 128), 256>>>(x, Wv, v, M_ROWS, KH_ * HD_, D_);

    // RoPE
    {
        int tq = B_ * S_ * QH_ * (HD_ / 2);
        int tk = B_ * S_ * KH_ * (HD_ / 2);
        rope_kernel<<<(tq + 255) / 256, 256>>>(q, positions, QH_, tq);
        rope_kernel<<<(tk + 255) / 256, 256>>>(k, positions, KH_, tk);
    }

    // Flash attention
    cudaFuncSetAttribute(flash_kernel, cudaFuncAttributeMaxDynamicSharedMemorySize,
                         FLASH_SMEM);
    flash_kernel<<<dim3(S_ / FBM, B_ * QH_), 256, FLASH_SMEM>>>(q, k, v, att);

    // Output projection: out = att @ Wo   (Wo flat is [QH*HD, D] row-major)
    sgemm128<false><<<dim3(D_ / 128, M_ROWS / 128), 256>>>(att, Wo, out, M_ROWS, D_,
                                                           QH_ * HD_);
}

// round 2
// speedup vs baseline: 1.0001x; 1.0001x over previous
#include <cuda_runtime.h>
#include <math.h>

// Problem dimensions (fixed by the dataset)
#define B_  2
#define S_  2048
#define D_  2048
#define QH_ 16
#define KH_ 4
#define HD_ 128
#define M_ROWS (B_ * S_)   // 4096

// ---------------------------------------------------------------------------
// Scratch (no allocations allowed -> __device__ globals)
// ---------------------------------------------------------------------------
__device__ float g_q[B_ * S_ * QH_ * HD_];   // 8M floats
__device__ float g_k[B_ * S_ * KH_ * HD_];   // 2M
__device__ float g_v[B_ * S_ * KH_ * HD_];   // 2M
__device__ float g_att[B_ * S_ * QH_ * HD_]; // 8M

// ---------------------------------------------------------------------------
// SGEMM: C[M,N] = A[M,K] @ W
//   HEADB=true : W is [n_heads, K, 128]; N-block bcol/128 selects the head,
//                within a head W is plain row-major [K,128].
//   HEADB=false: W is plain row-major [K,N].
// 128x128 block tile, 8-deep K slice, 8x8 register tile, 256 threads.
// ---------------------------------------------------------------------------
template <bool HEADB>
__global__ __launch_bounds__(256) void sgemm128(const float* __restrict__ A,
                                                const float* __restrict__ W,
                                                float* __restrict__ C,
                                                int M, int N, int K) {
    __shared__ float As[8][128];
    __shared__ float Bs[8][128];

    const int tid  = threadIdx.x;
    const int brow = blockIdx.y * 128;
    const int bcol = blockIdx.x * 128;

    const int a_row = tid >> 1;           // 0..127
    const int a_col = (tid & 1) << 2;     // 0 or 4
    const int b_row = tid >> 5;           // 0..7
    const int b_col = (tid & 31) << 2;    // 0..124

    const int tx = tid & 15;
    const int ty = tid >> 4;

    const float* Aptr = A + (size_t)(brow + a_row) * K + a_col;
    const float* Bptr;
    size_t b_kstride;
    if (HEADB) {
        // head = bcol / 128 == blockIdx.x
        Bptr = W + (size_t)blockIdx.x * K * 128 + (size_t)b_row * 128 + b_col;
        b_kstride = 128;
    } else {
        Bptr = W + (size_t)b_row * N + bcol + b_col;
        b_kstride = N;
    }

    float acc[8][8];
#pragma unroll
    for (int i = 0; i < 8; i++)
#pragma unroll
        for (int j = 0; j < 8; j++) acc[i][j] = 0.f;

    for (int k0 = 0; k0 < K; k0 += 8) {
        float4 av = *(const float4*)(Aptr + k0);
        float4 bv = *(const float4*)(Bptr + (size_t)k0 * b_kstride);
        As[a_col + 0][a_row] = av.x;
        As[a_col + 1][a_row] = av.y;
        As[a_col + 2][a_row] = av.z;
        As[a_col + 3][a_row] = av.w;
        *(float4*)&Bs[b_row][b_col] = bv;
        __syncthreads();

#pragma unroll
        for (int kk = 0; kk < 8; kk++) {
            float af[8], bf[8];
            float4 a0 = *(const float4*)&As[kk][ty * 8];
            float4 a1 = *(const float4*)&As[kk][ty * 8 + 4];
            float4 b0 = *(const float4*)&Bs[kk][tx * 8];
            float4 b1 = *(const float4*)&Bs[kk][tx * 8 + 4];
            af[0]=a0.x; af[1]=a0.y; af[2]=a0.z; af[3]=a0.w;
            af[4]=a1.x; af[5]=a1.y; af[6]=a1.z; af[7]=a1.w;
            bf[0]=b0.x; bf[1]=b0.y; bf[2]=b0.z; bf[3]=b0.w;
            bf[4]=b1.x; bf[5]=b1.y; bf[6]=b1.z; bf[7]=b1.w;
#pragma unroll
            for (int i = 0; i < 8; i++)
#pragma unroll
                for (int j = 0; j < 8; j++) acc[i][j] = fmaf(af[i], bf[j], acc[i][j]);
        }
        __syncthreads();
    }

#pragma unroll
    for (int i = 0; i < 8; i++) {
        size_t row = (size_t)brow + ty * 8 + i;
        float* cp = C + row * N + bcol + tx * 8;
        float4 c0 = make_float4(acc[i][0], acc[i][1], acc[i][2], acc[i][3]);
        float4 c1 = make_float4(acc[i][4], acc[i][5], acc[i][6], acc[i][7]);
        *(float4*)cp = c0;
        *(float4*)(cp + 4) = c1;
    }
}

// ---------------------------------------------------------------------------
// RoPE (in-place) on [B, S, NH, 128]
// ---------------------------------------------------------------------------
__global__ void rope_kernel(float* __restrict__ x, const int* __restrict__ positions,
                            int NH, int total) {
    int i = blockIdx.x * blockDim.x + threadIdx.x;
    if (i >= total) return;
    int hp = i & 63;            // 0..63 (half dim)
    int rest = i >> 6;
    int nh = rest % NH;
    int s  = (rest / NH) % S_;
    int b  = rest / (NH * S_);

    float pos = (float)positions[s];
    // timescale = 10000 ^ (hp/64), computed in fp32 like the reference
    float ts  = expf(((float)hp / 64.f) * 9.21034037197618f /* ln(1e4) */);
    float ang = pos / ts;
    float sn = sinf(ang);
    float cs = cosf(ang);

    size_t base = ((size_t)(b * S_ + s) * NH + nh) * HD_;
    float x1 = x[base + hp];
    float x2 = x[base + hp + 64];
    x[base + hp]      = x1 * cs - x2 * sn;
    x[base + hp + 64] = x2 * cs + x1 * sn;
}

// ---------------------------------------------------------------------------
// Flash attention (causal, GQA).  Grid: (S/64 query tiles, B*QH).
// Q,K kept transposed in smem ([h][row]) so the 64x64 score GEMM reads
// conflict-free float4s and the per-row softmax scan is a contiguous column.
// ---------------------------------------------------------------------------
#define FBM 64
#define FBN 64
#define QS 68   // FBM + 4 pad
#define KS 68
#define VS 132  // HD_ + 4 pad
#define PS 68

#define FLASH_SMEM ((HD_ * QS + HD_ * KS + FBN * VS + FBN * PS + 3 * FBM) * 4)

__global__ __launch_bounds__(256) void flash_kernel(const float* __restrict__ Q,
                                                    const float* __restrict__ K,
                                                    const float* __restrict__ V,
                                                    float* __restrict__ O) {
    extern __shared__ float sm[];
    float* Qst = sm;                    // [128][QS]
    float* Kst = Qst + HD_ * QS;        // [128][KS]
    float* Vs  = Kst + HD_ * KS;        // [64][VS]
    float* Pst = Vs + FBN * VS;         // [64][PS]  (P transposed: [j][i])
    float* rm  = Pst + FBN * PS;        // [64]
    float* rl  = rm + FBM;              // [64]
    float* rc  = rl + FBM;              // [64]

    const int tid = threadIdx.x;
    const int mblk = gridDim.x - 1 - blockIdx.x;   // heavy tiles first
    const int bq = blockIdx.y;
    const int b  = bq / QH_;
    const int qh = bq % QH_;
    const int kvh = qh / (QH_ / KH_);

    // Load Q tile, transposed into smem
    for (int idx = tid; idx < FBM * (HD_ / 4); idx += 256) {
        int r  = idx >> 5;
        int c4 = idx & 31;
        int s  = mblk * FBM + r;
        float4 v4 = *(const float4*)(Q + ((size_t)(b * S_ + s) * QH_ + qh) * HD_ + c4 * 4);
        int h = c4 * 4;
        Qst[(h + 0) * QS + r] = v4.x;
        Qst[(h + 1) * QS + r] = v4.y;
        Qst[(h + 2) * QS + r] = v4.z;
        Qst[(h + 3) * QS + r] = v4.w;
    }
    if (tid < FBM) { rm[tid] = -INFINITY; rl[tid] = 0.f; }

    const int ty = tid >> 4;   // 0..15
    const int tx = tid & 15;   // 0..15
    const int i0 = ty * 4;     // query row group
    const int j0 = tx * 4;     // score col group
    const int h0 = tx * 8;     // output dim group

    float oacc[4][8];
#pragma unroll
    for (int i = 0; i < 4; i++)
#pragma unroll
        for (int j = 0; j < 8; j++) oacc[i][j] = 0.f;

    const float scale = 0.08838834764831845f;  // 1/sqrt(128)

    for (int n = 0; n <= mblk; n++) {
        __syncthreads();  // protect Kst/Vs/Pst reuse (also covers Q-load for n==0)

        // Load K tile transposed, V tile direct
        for (int idx = tid; idx < FBN * (HD_ / 4); idx += 256) {
            int r  = idx >> 5;
            int c4 = idx & 31;
            int t  = n * FBN + r;
            size_t gbase = ((size_t)(b * S_ + t) * KH_ + kvh) * HD_ + c4 * 4;
            float4 kv = *(const float4*)(K + gbase);
            int h = c4 * 4;
            Kst[(h + 0) * KS + r] = kv.x;
            Kst[(h + 1) * KS + r] = kv.y;
            Kst[(h + 2) * KS + r] = kv.z;
            Kst[(h + 3) * KS + r] = kv.w;
            float4 vv = *(const float4*)(V + gbase);
            *(float4*)&Vs[r * VS + c4 * 4] = vv;
        }
        __syncthreads();

        // Scores: 4x4 per thread over h=0..127
        float sa[4][4];
#pragma unroll
        for (int i = 0; i < 4; i++)
#pragma unroll
            for (int j = 0; j < 4; j++) sa[i][j] = 0.f;

#pragma unroll 8
        for (int h = 0; h < HD_; h++) {
            float4 a = *(const float4*)&Qst[h * QS + i0];
            float4 bb = *(const float4*)&Kst[h * KS + j0];
            float af[4] = {a.x, a.y, a.z, a.w};
            float bf[4] = {bb.x, bb.y, bb.z, bb.w};
#pragma unroll
            for (int i = 0; i < 4; i++)
#pragma unroll
                for (int j = 0; j < 4; j++) sa[i][j] = fmaf(af[i], bf[j], sa[i][j]);
        }

        const int gi0 = mblk * FBM + i0;
        const int gj0 = n * FBN + j0;
#pragma unroll
        for (int j = 0; j < 4; j++)
#pragma unroll
            for (int i = 0; i < 4; i++) {
                float vx = sa[i][j] * scale;
                if (gj0 + j > gi0 + i) vx = -1e9f;
                Pst[(j0 + j) * PS + (i0 + i)] = vx;
            }
        __syncthreads();

        // Online softmax: one thread per query row (column scan of Pst)
        if (tid < FBM) {
            int i = tid;
            float mo = rm[i];
            float mx = mo;
#pragma unroll 8
            for (int j = 0; j < FBN; j++) mx = fmaxf(mx, Pst[j * PS + i]);
            float corr = __expf(mo - mx);
            float l = rl[i] * corr;
#pragma unroll 8
            for (int j = 0; j < FBN; j++) {
                float p = __expf(Pst[j * PS + i] - mx);
                Pst[j * PS + i] = p;
                l += p;
            }
            rm[i] = mx;
            rl[i] = l;
            rc[i] = corr;
        }
        __syncthreads();

        // Rescale O and accumulate P @ V  (4 rows x 8 dims per thread)
        float cr[4] = {rc[i0], rc[i0 + 1], rc[i0 + 2], rc[i0 + 3]};
#pragma unroll
        for (int i = 0; i < 4; i++)
#pragma unroll
            for (int j = 0; j < 8; j++) oacc[i][j] *= cr[i];

#pragma unroll 4
        for (int j = 0; j < FBN; j++) {
            float4 p4 = *(const float4*)&Pst[j * PS + i0];
            float4 v0 = *(const float4*)&Vs[j * VS + h0];
            float4 v1 = *(const float4*)&Vs[j * VS + h0 + 4];
            float pf[4] = {p4.x, p4.y, p4.z, p4.w};
            float vf[8] = {v0.x, v0.y, v0.z, v0.w, v1.x, v1.y, v1.z, v1.w};
#pragma unroll
            for (int i = 0; i < 4; i++)
#pragma unroll
                for (int hh = 0; hh < 8; hh++) oacc[i][hh] = fmaf(pf[i], vf[hh], oacc[i][hh]);
        }
    }

    // Epilogue: divide by row sum, write out [B,S,QH,H]
#pragma unroll
    for (int i = 0; i < 4; i++) {
        float inv = 1.0f / rl[i0 + i];
        int s = mblk * FBM + i0 + i;
        float* op = O + ((size_t)(b * S_ + s) * QH_ + qh) * HD_ + h0;
        float4 o0 = make_float4(oacc[i][0] * inv, oacc[i][1] * inv,
                                oacc[i][2] * inv, oacc[i][3] * inv);
        float4 o1 = make_float4(oacc[i][4] * inv, oacc[i][5] * inv,
                                oacc[i][6] * inv, oacc[i][7] * inv);
        *(float4*)op = o0;
        *(float4*)(op + 4) = o1;
    }
}

// ---------------------------------------------------------------------------
// Launch
// ---------------------------------------------------------------------------
extern "C" void kernel_launch(void* const* d_in, const int* in_sizes, int n_in,
                              void* d_out, int out_size) {
    const float* x         = (const float*)d_in[0];
    const int*   positions = (const int*)d_in[1];
    const float* Wq        = (const float*)d_in[2];
    const float* Wk        = (const float*)d_in[3];
    const float* Wv        = (const float*)d_in[4];
    const float* Wo        = (const float*)d_in[5];
    float* out = (float*)d_out;

    float *q, *k, *v, *att;
    cudaGetSymbolAddress((void**)&q,   g_q);
    cudaGetSymbolAddress((void**)&k,   g_k);
    cudaGetSymbolAddress((void**)&v,   g_v);
    cudaGetSymbolAddress((void**)&att, g_att);

    // Projections: q = x @ Wq (head-blocked), k/v likewise
    sgemm128<true><<<dim3(QH_, M_ROWS / 128), 256>>>(x, Wq, q, M_ROWS, QH_ * HD_, D_);
    sgemm128<true><<<dim3(KH_, M_ROWS / 128), 256>>>(x, Wk, k, M_ROWS, KH_ * HD_, D_);
    sgemm128<true><<<dim3(KH_, M_ROWS / 128), 256>>>(x, Wv, v, M_ROWS, KH_ * HD_, D_);

    // RoPE
    {
        int tq = B_ * S_ * QH_ * (HD_ / 2);
        int tk = B_ * S_ * KH_ * (HD_ / 2);
        rope_kernel<<<(tq + 255) / 256, 256>>>(q, positions, QH_, tq);
        rope_kernel<<<(tk + 255) / 256, 256>>>(k, positions, KH_, tk);
    }

    // Flash attention
    cudaFuncSetAttribute(flash_kernel, cudaFuncAttributeMaxDynamicSharedMemorySize,
                         FLASH_SMEM);
    flash_kernel<<<dim3(S_ / FBM, B_ * QH_), 256, FLASH_SMEM>>>(q, k, v, att);

    // Output projection: out = att @ Wo   (Wo flat is [QH*HD, D] row-major)
    sgemm128<false><<<dim3(D_ / 128, M_ROWS / 128), 256>>>(att, Wo, out, M_ROWS, D_,
                                                           QH_ * HD_);
}

// round 3
// speedup vs baseline: 1.7446x; 1.7445x over previous
#include <cuda_runtime.h>
#include <math.h>
#include <stdint.h>

// Problem dimensions (fixed by the dataset)
#define B_  2
#define S_  2048
#define D_  2048
#define QH_ 16
#define KH_ 4
#define HD_ 128
#define M_ROWS (B_ * S_)   // 4096

// ---------------------------------------------------------------------------
// Scratch (no allocations allowed -> __device__ globals)
// ---------------------------------------------------------------------------
__device__ float g_q[B_ * S_ * QH_ * HD_];   // 8M floats
__device__ float g_k[B_ * S_ * KH_ * HD_];   // 2M
__device__ float g_v[B_ * S_ * KH_ * HD_];   // 2M
__device__ float g_att[B_ * S_ * QH_ * HD_]; // 8M

// ---------------------------------------------------------------------------
// TF32 helpers
// ---------------------------------------------------------------------------
__device__ __forceinline__ uint32_t f2tf32(float f) {
    uint32_t u;
    asm("cvt.rna.tf32.f32 %0, %1;" : "=r"(u) : "f"(f));
    return u;
}

__device__ __forceinline__ void mma_tf32(float* c, const uint32_t* a, const uint32_t* b) {
    asm volatile(
        "mma.sync.aligned.m16n8k8.row.col.f32.tf32.tf32.f32 "
        "{%0,%1,%2,%3}, {%4,%5,%6,%7}, {%8,%9}, {%0,%1,%2,%3};\n"
        : "+f"(c[0]), "+f"(c[1]), "+f"(c[2]), "+f"(c[3])
        : "r"(a[0]), "r"(a[1]), "r"(a[2]), "r"(a[3]), "r"(b[0]), "r"(b[1]));
}

// ---------------------------------------------------------------------------
// TF32 tensor-core GEMM: C[M,N] = A[M,K] @ W
//   HEADB=true : W is [n_heads, K, 128]; blockIdx.x selects the head,
//                within a head W is row-major [K,128].
//   HEADB=false: W is plain row-major [K,N].
// 128x128 block tile, BK=32, 256 threads = 8 warps (2x4), warp tile 64x32,
// mma.m16n8k8: per warp 4 M-frags x 4 N-frags, 4 k-steps per BK.
// Smem: As[m][k] stride 36 (A-frag bank = 4m+k, conflict-free)
//       Bs[k][n] stride 136 (B-frag bank = 8k+g, conflict-free)
// ---------------------------------------------------------------------------
template <bool HEADB>
__global__ __launch_bounds__(256) void gemm_tf32(const float* __restrict__ A,
                                                 const float* __restrict__ W,
                                                 float* __restrict__ C,
                                                 int M, int N, int K) {
    __shared__ uint32_t As[128 * 36];
    __shared__ uint32_t Bs[32 * 136];

    const int tid  = threadIdx.x;
    const int lane = tid & 31;
    const int wid  = tid >> 5;
    const int warpm = wid >> 2;   // 0..1
    const int warpn = wid & 3;    // 0..3
    const int g = lane >> 2;      // 0..7
    const int q = lane & 3;       // 0..3

    const int brow = blockIdx.y * 128;
    const int bcol = blockIdx.x * 128;

    // loader mappings
    const int am  = tid >> 3;          // 0..31 (row within 32-row pass)
    const int ak4 = (tid & 7) << 2;    // 0,4,...,28
    const int bk  = tid >> 5;          // 0..7
    const int bn4 = (tid & 31) << 2;   // 0..124

    const float* Aptr = A + (size_t)(brow + am) * K + ak4;
    const float* Wptr;
    int wstride;
    if (HEADB) {
        Wptr = W + (size_t)blockIdx.x * K * 128 + (size_t)bk * 128 + bn4;
        wstride = 128;
    } else {
        Wptr = W + (size_t)bk * N + bcol + bn4;
        wstride = N;
    }

    float acc[4][4][4];
#pragma unroll
    for (int mt = 0; mt < 4; mt++)
#pragma unroll
        for (int nt = 0; nt < 4; nt++)
#pragma unroll
            for (int i = 0; i < 4; i++) acc[mt][nt][i] = 0.f;

    for (int k0 = 0; k0 < K; k0 += 32) {
        // ---- stage A tile (128 x 32) ----
#pragma unroll
        for (int p = 0; p < 4; p++) {
            float4 v = *(const float4*)(Aptr + (size_t)(p * 32) * K + k0);
            uint4 t = make_uint4(f2tf32(v.x), f2tf32(v.y), f2tf32(v.z), f2tf32(v.w));
            *(uint4*)&As[(am + 32 * p) * 36 + ak4] = t;
        }
        // ---- stage B tile (32 x 128) ----
#pragma unroll
        for (int p = 0; p < 4; p++) {
            float4 v = *(const float4*)(Wptr + (size_t)(k0 + p * 8) * wstride);
            uint4 t = make_uint4(f2tf32(v.x), f2tf32(v.y), f2tf32(v.z), f2tf32(v.w));
            *(uint4*)&Bs[(bk + 8 * p) * 136 + bn4] = t;
        }
        __syncthreads();

#pragma unroll
        for (int kk = 0; kk < 4; kk++) {
            const int kc = kk * 8;
            uint32_t af[4][4];
            uint32_t bf[4][2];
#pragma unroll
            for (int mt = 0; mt < 4; mt++) {
                int r = warpm * 64 + mt * 16 + g;
                af[mt][0] = As[r * 36 + kc + q];
                af[mt][1] = As[(r + 8) * 36 + kc + q];
                af[mt][2] = As[r * 36 + kc + q + 4];
                af[mt][3] = As[(r + 8) * 36 + kc + q + 4];
            }
#pragma unroll
            for (int nt = 0; nt < 4; nt++) {
                int c = warpn * 32 + nt * 8 + g;
                bf[nt][0] = Bs[(kc + q) * 136 + c];
                bf[nt][1] = Bs[(kc + q + 4) * 136 + c];
            }
#pragma unroll
            for (int mt = 0; mt < 4; mt++)
#pragma unroll
                for (int nt = 0; nt < 4; nt++)
                    mma_tf32(acc[mt][nt], af[mt], bf[nt]);
        }
        __syncthreads();
    }

    // ---- epilogue ----
#pragma unroll
    for (int mt = 0; mt < 4; mt++) {
        int r = brow + warpm * 64 + mt * 16 + g;
#pragma unroll
        for (int nt = 0; nt < 4; nt++) {
            int c = bcol + warpn * 32 + nt * 8 + 2 * q;
            *(float2*)&C[(size_t)r * N + c] = make_float2(acc[mt][nt][0], acc[mt][nt][1]);
            *(float2*)&C[(size_t)(r + 8) * N + c] = make_float2(acc[mt][nt][2], acc[mt][nt][3]);
        }
    }
}

// ---------------------------------------------------------------------------
// RoPE (in-place) on [B, S, NH, 128]
// ---------------------------------------------------------------------------
__global__ void rope_kernel(float* __restrict__ x, const int* __restrict__ positions,
                            int NH, int total) {
    int i = blockIdx.x * blockDim.x + threadIdx.x;
    if (i >= total) return;
    int hp = i & 63;            // 0..63 (half dim)
    int rest = i >> 6;
    int nh = rest % NH;
    int s  = (rest / NH) % S_;
    int b  = rest / (NH * S_);

    float pos = (float)positions[s];
    float ts  = expf(((float)hp / 64.f) * 9.21034037197618f /* ln(1e4) */);
    float ang = pos / ts;
    float sn = sinf(ang);
    float cs = cosf(ang);

    size_t base = ((size_t)(b * S_ + s) * NH + nh) * HD_;
    float x1 = x[base + hp];
    float x2 = x[base + hp + 64];
    x[base + hp]      = x1 * cs - x2 * sn;
    x[base + hp + 64] = x2 * cs + x1 * sn;
}

// ---------------------------------------------------------------------------
// Flash attention (causal, GQA).  Grid: (S/64 query tiles, B*QH).
// fp32 CUDA-core version (unchanged from R1 — converted to tensor cores next).
// ---------------------------------------------------------------------------
#define FBM 64
#define FBN 64
#define QS 68
#define KS 68
#define VS 132
#define PS 68

#define FLASH_SMEM ((HD_ * QS + HD_ * KS + FBN * VS + FBN * PS + 3 * FBM) * 4)

__global__ __launch_bounds__(256) void flash_kernel(const float* __restrict__ Q,
                                                    const float* __restrict__ K,
                                                    const float* __restrict__ V,
                                                    float* __restrict__ O) {
    extern __shared__ float sm[];
    float* Qst = sm;                    // [128][QS]
    float* Kst = Qst + HD_ * QS;        // [128][KS]
    float* Vs  = Kst + HD_ * KS;        // [64][VS]
    float* Pst = Vs + FBN * VS;         // [64][PS]
    float* rm  = Pst + FBN * PS;        // [64]
    float* rl  = rm + FBM;              // [64]
    float* rc  = rl + FBM;              // [64]

    const int tid = threadIdx.x;
    const int mblk = gridDim.x - 1 - blockIdx.x;   // heavy tiles first
    const int bq = blockIdx.y;
    const int b  = bq / QH_;
    const int qh = bq % QH_;
    const int kvh = qh / (QH_ / KH_);

    for (int idx = tid; idx < FBM * (HD_ / 4); idx += 256) {
        int r  = idx >> 5;
        int c4 = idx & 31;
        int s  = mblk * FBM + r;
        float4 v4 = *(const float4*)(Q + ((size_t)(b * S_ + s) * QH_ + qh) * HD_ + c4 * 4);
        int h = c4 * 4;
        Qst[(h + 0) * QS + r] = v4.x;
        Qst[(h + 1) * QS + r] = v4.y;
        Qst[(h + 2) * QS + r] = v4.z;
        Qst[(h + 3) * QS + r] = v4.w;
    }
    if (tid < FBM) { rm[tid] = -INFINITY; rl[tid] = 0.f; }

    const int ty = tid >> 4;
    const int tx = tid & 15;
    const int i0 = ty * 4;
    const int j0 = tx * 4;
    const int h0 = tx * 8;

    float oacc[4][8];
#pragma unroll
    for (int i = 0; i < 4; i++)
#pragma unroll
        for (int j = 0; j < 8; j++) oacc[i][j] = 0.f;

    const float scale = 0.08838834764831845f;  // 1/sqrt(128)

    for (int n = 0; n <= mblk; n++) {
        __syncthreads();

        for (int idx = tid; idx < FBN * (HD_ / 4); idx += 256) {
            int r  = idx >> 5;
            int c4 = idx & 31;
            int t  = n * FBN + r;
            size_t gbase = ((size_t)(b * S_ + t) * KH_ + kvh) * HD_ + c4 * 4;
            float4 kv = *(const float4*)(K + gbase);
            int h = c4 * 4;
            Kst[(h + 0) * KS + r] = kv.x;
            Kst[(h + 1) * KS + r] = kv.y;
            Kst[(h + 2) * KS + r] = kv.z;
            Kst[(h + 3) * KS + r] = kv.w;
            float4 vv = *(const float4*)(V + gbase);
            *(float4*)&Vs[r * VS + c4 * 4] = vv;
        }
        __syncthreads();

        float sa[4][4];
#pragma unroll
        for (int i = 0; i < 4; i++)
#pragma unroll
            for (int j = 0; j < 4; j++) sa[i][j] = 0.f;

#pragma unroll 8
        for (int h = 0; h < HD_; h++) {
            float4 a = *(const float4*)&Qst[h * QS + i0];
            float4 bb = *(const float4*)&Kst[h * KS + j0];
            float af[4] = {a.x, a.y, a.z, a.w};
            float bf[4] = {bb.x, bb.y, bb.z, bb.w};
#pragma unroll
            for (int i = 0; i < 4; i++)
#pragma unroll
                for (int j = 0; j < 4; j++) sa[i][j] = fmaf(af[i], bf[j], sa[i][j]);
        }

        const int gi0 = mblk * FBM + i0;
        const int gj0 = n * FBN + j0;
#pragma unroll
        for (int j = 0; j < 4; j++)
#pragma unroll
            for (int i = 0; i < 4; i++) {
                float vx = sa[i][j] * scale;
                if (gj0 + j > gi0 + i) vx = -1e9f;
                Pst[(j0 + j) * PS + (i0 + i)] = vx;
            }
        __syncthreads();

        if (tid < FBM) {
            int i = tid;
            float mo = rm[i];
            float mx = mo;
#pragma unroll 8
            for (int j = 0; j < FBN; j++) mx = fmaxf(mx, Pst[j * PS + i]);
            float corr = __expf(mo - mx);
            float l = rl[i] * corr;
#pragma unroll 8
            for (int j = 0; j < FBN; j++) {
                float p = __expf(Pst[j * PS + i] - mx);
                Pst[j * PS + i] = p;
                l += p;
            }
            rm[i] = mx;
            rl[i] = l;
            rc[i] = corr;
        }
        __syncthreads();

        float cr[4] = {rc[i0], rc[i0 + 1], rc[i0 + 2], rc[i0 + 3]};
#pragma unroll
        for (int i = 0; i < 4; i++)
#pragma unroll
            for (int j = 0; j < 8; j++) oacc[i][j] *= cr[i];

#pragma unroll 4
        for (int j = 0; j < FBN; j++) {
            float4 p4 = *(const float4*)&Pst[j * PS + i0];
            float4 v0 = *(const float4*)&Vs[j * VS + h0];
            float4 v1 = *(const float4*)&Vs[j * VS + h0 + 4];
            float pf[4] = {p4.x, p4.y, p4.z, p4.w};
            float vf[8] = {v0.x, v0.y, v0.z, v0.w, v1.x, v1.y, v1.z, v1.w};
#pragma unroll
            for (int i = 0; i < 4; i++)
#pragma unroll
                for (int hh = 0; hh < 8; hh++) oacc[i][hh] = fmaf(pf[i], vf[hh], oacc[i][hh]);
        }
    }

#pragma unroll
    for (int i = 0; i < 4; i++) {
        float inv = 1.0f / rl[i0 + i];
        int s = mblk * FBM + i0 + i;
        float* op = O + ((size_t)(b * S_ + s) * QH_ + qh) * HD_ + h0;
        float4 o0 = make_float4(oacc[i][0] * inv, oacc[i][1] * inv,
                                oacc[i][2] * inv, oacc[i][3] * inv);
        float4 o1 = make_float4(oacc[i][4] * inv, oacc[i][5] * inv,
                                oacc[i][6] * inv, oacc[i][7] * inv);
        *(float4*)op = o0;
        *(float4*)(op + 4) = o1;
    }
}

// ---------------------------------------------------------------------------
// Launch
// ---------------------------------------------------------------------------
extern "C" void kernel_launch(void* const* d_in, const int* in_sizes, int n_in,
                              void* d_out, int out_size) {
    const float* x         = (const float*)d_in[0];
    const int*   positions = (const int*)d_in[1];
    const float* Wq        = (const float*)d_in[2];
    const float* Wk        = (const float*)d_in[3];
    const float* Wv        = (const float*)d_in[4];
    const float* Wo        = (const float*)d_in[5];
    float* out = (float*)d_out;

    float *q, *k, *v, *att;
    cudaGetSymbolAddress((void**)&q,   g_q);
    cudaGetSymbolAddress((void**)&k,   g_k);
    cudaGetSymbolAddress((void**)&v,   g_v);
    cudaGetSymbolAddress((void**)&att, g_att);

    // Projections on tensor cores (TF32)
    gemm_tf32<true><<<dim3(QH_, M_ROWS / 128), 256>>>(x, Wq, q, M_ROWS, QH_ * HD_, D_);
    gemm_tf32<true><<<dim3(KH_, M_ROWS / 128), 256>>>(x, Wk, k, M_ROWS, KH_ * HD_, D_);
    gemm_tf32<true><<<dim3(KH_, M_ROWS / 128), 256>>>(x, Wv, v, M_ROWS, KH_ * HD_, D_);

    // RoPE
    {
        int tq = B_ * S_ * QH_ * (HD_ / 2);
        int tk = B_ * S_ * KH_ * (HD_ / 2);
        rope_kernel<<<(tq + 255) / 256, 256>>>(q, positions, QH_, tq);
        rope_kernel<<<(tk + 255) / 256, 256>>>(k, positions, KH_, tk);
    }

    // Flash attention (fp32 for now)
    cudaFuncSetAttribute(flash_kernel, cudaFuncAttributeMaxDynamicSharedMemorySize,
                         FLASH_SMEM);
    flash_kernel<<<dim3(S_ / FBM, B_ * QH_), 256, FLASH_SMEM>>>(q, k, v, att);

    // Output projection on tensor cores (Wo flat is [QH*HD, D] row-major)
    gemm_tf32<false><<<dim3(D_ / 128, M_ROWS / 128), 256>>>(att, Wo, out, M_ROWS, D_,
                                                            QH_ * HD_);
}

// round 4
// speedup vs baseline: 3.4367x; 1.9699x over previous
#include <cuda_runtime.h>
#include <math.h>
#include <stdint.h>

// Problem dimensions (fixed by the dataset)
#define B_  2
#define S_  2048
#define D_  2048
#define QH_ 16
#define KH_ 4
#define HD_ 128
#define M_ROWS (B_ * S_)   // 4096

// ---------------------------------------------------------------------------
// Scratch (no allocations allowed -> __device__ globals)
// ---------------------------------------------------------------------------
__device__ float g_q[B_ * S_ * QH_ * HD_];   // 8M floats
__device__ float g_k[B_ * S_ * KH_ * HD_];   // 2M
__device__ float g_v[B_ * S_ * KH_ * HD_];   // 2M
__device__ float g_att[B_ * S_ * QH_ * HD_]; // 8M

// ---------------------------------------------------------------------------
// TF32 helpers
// ---------------------------------------------------------------------------
__device__ __forceinline__ uint32_t f2tf32(float f) {
    uint32_t u;
    asm("cvt.rna.tf32.f32 %0, %1;" : "=r"(u) : "f"(f));
    return u;
}

__device__ __forceinline__ void mma_tf32(float* c, const uint32_t* a, const uint32_t* b) {
    asm volatile(
        "mma.sync.aligned.m16n8k8.row.col.f32.tf32.tf32.f32 "
        "{%0,%1,%2,%3}, {%4,%5,%6,%7}, {%8,%9}, {%0,%1,%2,%3};\n"
        : "+f"(c[0]), "+f"(c[1]), "+f"(c[2]), "+f"(c[3])
        : "r"(a[0]), "r"(a[1]), "r"(a[2]), "r"(a[3]), "r"(b[0]), "r"(b[1]));
}

// ---------------------------------------------------------------------------
// TF32 tensor-core GEMM (unchanged from R2): C[M,N] = A[M,K] @ W
// ---------------------------------------------------------------------------
template <bool HEADB>
__global__ __launch_bounds__(256) void gemm_tf32(const float* __restrict__ A,
                                                 const float* __restrict__ W,
                                                 float* __restrict__ C,
                                                 int M, int N, int K) {
    __shared__ uint32_t As[128 * 36];
    __shared__ uint32_t Bs[32 * 136];

    const int tid  = threadIdx.x;
    const int lane = tid & 31;
    const int wid  = tid >> 5;
    const int warpm = wid >> 2;
    const int warpn = wid & 3;
    const int g = lane >> 2;
    const int q = lane & 3;

    const int brow = blockIdx.y * 128;
    const int bcol = blockIdx.x * 128;

    const int am  = tid >> 3;
    const int ak4 = (tid & 7) << 2;
    const int bk  = tid >> 5;
    const int bn4 = (tid & 31) << 2;

    const float* Aptr = A + (size_t)(brow + am) * K + ak4;
    const float* Wptr;
    int wstride;
    if (HEADB) {
        Wptr = W + (size_t)blockIdx.x * K * 128 + (size_t)bk * 128 + bn4;
        wstride = 128;
    } else {
        Wptr = W + (size_t)bk * N + bcol + bn4;
        wstride = N;
    }

    float acc[4][4][4];
#pragma unroll
    for (int mt = 0; mt < 4; mt++)
#pragma unroll
        for (int nt = 0; nt < 4; nt++)
#pragma unroll
            for (int i = 0; i < 4; i++) acc[mt][nt][i] = 0.f;

    for (int k0 = 0; k0 < K; k0 += 32) {
#pragma unroll
        for (int p = 0; p < 4; p++) {
            float4 v = *(const float4*)(Aptr + (size_t)(p * 32) * K + k0);
            uint4 t = make_uint4(f2tf32(v.x), f2tf32(v.y), f2tf32(v.z), f2tf32(v.w));
            *(uint4*)&As[(am + 32 * p) * 36 + ak4] = t;
        }
#pragma unroll
        for (int p = 0; p < 4; p++) {
            float4 v = *(const float4*)(Wptr + (size_t)(k0 + p * 8) * wstride);
            uint4 t = make_uint4(f2tf32(v.x), f2tf32(v.y), f2tf32(v.z), f2tf32(v.w));
            *(uint4*)&Bs[(bk + 8 * p) * 136 + bn4] = t;
        }
        __syncthreads();

#pragma unroll
        for (int kk = 0; kk < 4; kk++) {
            const int kc = kk * 8;
            uint32_t af[4][4];
            uint32_t bf[4][2];
#pragma unroll
            for (int mt = 0; mt < 4; mt++) {
                int r = warpm * 64 + mt * 16 + g;
                af[mt][0] = As[r * 36 + kc + q];
                af[mt][1] = As[(r + 8) * 36 + kc + q];
                af[mt][2] = As[r * 36 + kc + q + 4];
                af[mt][3] = As[(r + 8) * 36 + kc + q + 4];
            }
#pragma unroll
            for (int nt = 0; nt < 4; nt++) {
                int c = warpn * 32 + nt * 8 + g;
                bf[nt][0] = Bs[(kc + q) * 136 + c];
                bf[nt][1] = Bs[(kc + q + 4) * 136 + c];
            }
#pragma unroll
            for (int mt = 0; mt < 4; mt++)
#pragma unroll
                for (int nt = 0; nt < 4; nt++)
                    mma_tf32(acc[mt][nt], af[mt], bf[nt]);
        }
        __syncthreads();
    }

#pragma unroll
    for (int mt = 0; mt < 4; mt++) {
        int r = brow + warpm * 64 + mt * 16 + g;
#pragma unroll
        for (int nt = 0; nt < 4; nt++) {
            int c = bcol + warpn * 32 + nt * 8 + 2 * q;
            *(float2*)&C[(size_t)r * N + c] = make_float2(acc[mt][nt][0], acc[mt][nt][1]);
            *(float2*)&C[(size_t)(r + 8) * N + c] = make_float2(acc[mt][nt][2], acc[mt][nt][3]);
        }
    }
}

// ---------------------------------------------------------------------------
// RoPE (in-place) on [B, S, NH, 128]
// ---------------------------------------------------------------------------
__global__ void rope_kernel(float* __restrict__ x, const int* __restrict__ positions,
                            int NH, int total) {
    int i = blockIdx.x * blockDim.x + threadIdx.x;
    if (i >= total) return;
    int hp = i & 63;
    int rest = i >> 6;
    int nh = rest % NH;
    int s  = (rest / NH) % S_;
    int b  = rest / (NH * S_);

    float pos = (float)positions[s];
    float ts  = expf(((float)hp / 64.f) * 9.21034037197618f /* ln(1e4) */);
    float ang = pos / ts;
    float sn = sinf(ang);
    float cs = cosf(ang);

    size_t base = ((size_t)(b * S_ + s) * NH + nh) * HD_;
    float x1 = x[base + hp];
    float x2 = x[base + hp + 64];
    x[base + hp]      = x1 * cs - x2 * sn;
    x[base + hp + 64] = x2 * cs + x1 * sn;
}

// ---------------------------------------------------------------------------
// Flash attention, TF32 tensor cores (causal, GQA).
// Grid: (S/64 query tiles [reversed: heavy first], B*QH).
// 256 threads = 8 warps as 2(m) x 4(n).
// QK: per-warp 32x16 slice of the 64x64 score tile, K=128.
// PV: per-warp 32x32 slice of the 64x128 output tile, K=64.
// Smem strides chosen for conflict-free mma fragment LDS:
//   Qs/Ks stride 132 (bank 4g+q), Vs stride 136 (bank 8q+g), Ps stride 68.
// ---------------------------------------------------------------------------
#define FQS 132
#define FKS 132
#define FVS 136
#define FPS 68

#define FLASH_SMEM ((64 * FQS + 64 * FKS + 64 * FVS + 64 * FPS + 2 * 256 + 2 * 64) * 4)

__global__ __launch_bounds__(256) void flash_tc(const float* __restrict__ Q,
                                                const float* __restrict__ K,
                                                const float* __restrict__ V,
                                                float* __restrict__ O) {
    extern __shared__ uint32_t sm_u[];
    uint32_t* Qs = sm_u;                 // [64][132]
    uint32_t* Ks = Qs + 64 * FQS;        // [64][132]
    uint32_t* Vs = Ks + 64 * FKS;        // [64][136]  natural [key][h]
    uint32_t* Ps = Vs + 64 * FVS;        // [64][68]   [row][key]
    float* smax  = (float*)(Ps + 64 * FPS);  // [4][64]
    float* ssum  = smax + 256;               // [4][64]
    float* rm    = ssum + 256;               // [64]
    float* rl    = rm + 64;                  // [64]

    const int tid  = threadIdx.x;
    const int lane = tid & 31;
    const int wid  = tid >> 5;
    const int warpm = wid >> 2;   // 0..1
    const int warpn = wid & 3;    // 0..3
    const int g = lane >> 2;      // 0..7
    const int q = lane & 3;       // 0..3

    const int mblk = gridDim.x - 1 - blockIdx.x;   // heavy tiles first
    const int bq = blockIdx.y;
    const int b  = bq / QH_;
    const int qh = bq % QH_;
    const int kvh = qh / (QH_ / KH_);

    // Load Q tile [64][128] (natural, tf32)
    for (int idx = tid; idx < 64 * 32; idx += 256) {
        int r  = idx >> 5;
        int c4 = (idx & 31) << 2;
        float4 v4 = *(const float4*)(Q + ((size_t)(b * S_ + mblk * 64 + r) * QH_ + qh) * HD_ + c4);
        uint4 t = make_uint4(f2tf32(v4.x), f2tf32(v4.y), f2tf32(v4.z), f2tf32(v4.w));
        *(uint4*)&Qs[r * FQS + c4] = t;
    }
    if (tid < 64) { rm[tid] = -INFINITY; rl[tid] = 0.f; }

    float o[2][4][4];
#pragma unroll
    for (int mt = 0; mt < 2; mt++)
#pragma unroll
        for (int nt = 0; nt < 4; nt++)
#pragma unroll
            for (int i = 0; i < 4; i++) o[mt][nt][i] = 0.f;

    const float scale = 0.08838834764831845f;  // 1/sqrt(128)
    const int row_base = warpm * 32 + g;       // + mt*16 (+8)
    const int qkcol_base = warpn * 16 + 2 * q; // + nt*8 (+1)

    for (int n = 0; n <= mblk; n++) {
        __syncthreads();

        // Load K tile [64][128] natural
        for (int idx = tid; idx < 64 * 32; idx += 256) {
            int r  = idx >> 5;
            int c4 = (idx & 31) << 2;
            float4 kv = *(const float4*)(K + ((size_t)(b * S_ + n * 64 + r) * KH_ + kvh) * HD_ + c4);
            uint4 t = make_uint4(f2tf32(kv.x), f2tf32(kv.y), f2tf32(kv.z), f2tf32(kv.w));
            *(uint4*)&Ks[r * FKS + c4] = t;
        }
        // Load V tile [64][128] natural
        for (int idx = tid; idx < 64 * 32; idx += 256) {
            int r  = idx >> 5;
            int c4 = (idx & 31) << 2;
            float4 vv = *(const float4*)(V + ((size_t)(b * S_ + n * 64 + r) * KH_ + kvh) * HD_ + c4);
            uint4 t = make_uint4(f2tf32(vv.x), f2tf32(vv.y), f2tf32(vv.z), f2tf32(vv.w));
            *(uint4*)&Vs[r * FVS + c4] = t;
        }
        __syncthreads();

        // ---- QK^T: s[2][2][4] ----
        float s[2][2][4];
#pragma unroll
        for (int mt = 0; mt < 2; mt++)
#pragma unroll
            for (int nt = 0; nt < 2; nt++)
#pragma unroll
                for (int i = 0; i < 4; i++) s[mt][nt][i] = 0.f;

#pragma unroll
        for (int ks = 0; ks < 16; ks++) {
            const int kc = ks * 8;
            uint32_t af[2][4], bf[2][2];
#pragma unroll
            for (int mt = 0; mt < 2; mt++) {
                int r = warpm * 32 + mt * 16 + g;
                af[mt][0] = Qs[r * FQS + kc + q];
                af[mt][1] = Qs[(r + 8) * FQS + kc + q];
                af[mt][2] = Qs[r * FQS + kc + q + 4];
                af[mt][3] = Qs[(r + 8) * FQS + kc + q + 4];
            }
#pragma unroll
            for (int nt = 0; nt < 2; nt++) {
                int c = warpn * 16 + nt * 8 + g;
                bf[nt][0] = Ks[c * FKS + kc + q];
                bf[nt][1] = Ks[c * FKS + kc + q + 4];
            }
#pragma unroll
            for (int mt = 0; mt < 2; mt++)
#pragma unroll
                for (int nt = 0; nt < 2; nt++)
                    mma_tf32(s[mt][nt], af[mt], bf[nt]);
        }

        // ---- scale + causal mask (in regs) ----
        const int gr_base = mblk * 64 + row_base;
        const int gc_base = n * 64 + qkcol_base;
#pragma unroll
        for (int mt = 0; mt < 2; mt++) {
            int gr0 = gr_base + mt * 16;
            int gr1 = gr0 + 8;
#pragma unroll
            for (int nt = 0; nt < 2; nt++) {
                int gc0 = gc_base + nt * 8;
                int gc1 = gc0 + 1;
                s[mt][nt][0] = (gc0 > gr0) ? -1e9f : s[mt][nt][0] * scale;
                s[mt][nt][1] = (gc1 > gr0) ? -1e9f : s[mt][nt][1] * scale;
                s[mt][nt][2] = (gc0 > gr1) ? -1e9f : s[mt][nt][2] * scale;
                s[mt][nt][3] = (gc1 > gr1) ? -1e9f : s[mt][nt][3] * scale;
            }
        }

        // ---- partial row max -> smax ----
#pragma unroll
        for (int mt = 0; mt < 2; mt++)
#pragma unroll
            for (int h = 0; h < 2; h++) {
                float pm = fmaxf(fmaxf(s[mt][0][2 * h], s[mt][0][2 * h + 1]),
                                 fmaxf(s[mt][1][2 * h], s[mt][1][2 * h + 1]));
                pm = fmaxf(pm, __shfl_xor_sync(0xFFFFFFFF, pm, 1));
                pm = fmaxf(pm, __shfl_xor_sync(0xFFFFFFFF, pm, 2));
                if (q == 0) smax[warpn * 64 + row_base + mt * 16 + 8 * h] = pm;
            }
        __syncthreads();

        // ---- exp + partial sums, P to smem (tf32) ----
        float corr[2][2];
#pragma unroll
        for (int mt = 0; mt < 2; mt++)
#pragma unroll
            for (int h = 0; h < 2; h++) {
                int row = row_base + mt * 16 + 8 * h;
                float m_tile = fmaxf(fmaxf(smax[row], smax[64 + row]),
                                     fmaxf(smax[128 + row], smax[192 + row]));
                float m_old = rm[row];
                float m_new = fmaxf(m_old, m_tile);
                corr[mt][h] = __expf(m_old - m_new);

                float psum = 0.f;
#pragma unroll
                for (int nt = 0; nt < 2; nt++) {
                    float p0 = __expf(s[mt][nt][2 * h] - m_new);
                    float p1 = __expf(s[mt][nt][2 * h + 1] - m_new);
                    psum += p0 + p1;
                    int col = qkcol_base + nt * 8;
                    *(uint2*)&Ps[row * FPS + col] = make_uint2(f2tf32(p0), f2tf32(p1));
                }
                psum += __shfl_xor_sync(0xFFFFFFFF, psum, 1);
                psum += __shfl_xor_sync(0xFFFFFFFF, psum, 2);
                if (q == 0) ssum[warpn * 64 + row] = psum;
                if (warpn == 0 && q == 0) rm[row] = m_new;
            }
        __syncthreads();

        // ---- l update ----
        if (warpn == 0 && q == 0) {
#pragma unroll
            for (int mt = 0; mt < 2; mt++)
#pragma unroll
                for (int h = 0; h < 2; h++) {
                    int row = row_base + mt * 16 + 8 * h;
                    float ts = ssum[row] + ssum[64 + row] + ssum[128 + row] + ssum[192 + row];
                    rl[row] = rl[row] * corr[mt][h] + ts;
                }
        }

        // ---- rescale O, then PV mma ----
#pragma unroll
        for (int mt = 0; mt < 2; mt++)
#pragma unroll
            for (int nt = 0; nt < 4; nt++) {
                o[mt][nt][0] *= corr[mt][0];
                o[mt][nt][1] *= corr[mt][0];
                o[mt][nt][2] *= corr[mt][1];
                o[mt][nt][3] *= corr[mt][1];
            }

#pragma unroll
        for (int ks = 0; ks < 8; ks++) {
            const int kc = ks * 8;
            uint32_t af[2][4], bf[4][2];
#pragma unroll
            for (int mt = 0; mt < 2; mt++) {
                int r = warpm * 32 + mt * 16 + g;
                af[mt][0] = Ps[r * FPS + kc + q];
                af[mt][1] = Ps[(r + 8) * FPS + kc + q];
                af[mt][2] = Ps[r * FPS + kc + q + 4];
                af[mt][3] = Ps[(r + 8) * FPS + kc + q + 4];
            }
#pragma unroll
            for (int nt = 0; nt < 4; nt++) {
                int c = warpn * 32 + nt * 8 + g;
                bf[nt][0] = Vs[(kc + q) * FVS + c];
                bf[nt][1] = Vs[(kc + q + 4) * FVS + c];
            }
#pragma unroll
            for (int mt = 0; mt < 2; mt++)
#pragma unroll
                for (int nt = 0; nt < 4; nt++)
                    mma_tf32(o[mt][nt], af[mt], bf[nt]);
        }
    }

    // ---- epilogue ----
#pragma unroll
    for (int mt = 0; mt < 2; mt++) {
        float inv0 = 1.0f / rl[row_base + mt * 16];
        float inv1 = 1.0f / rl[row_base + mt * 16 + 8];
        int s0 = mblk * 64 + row_base + mt * 16;
#pragma unroll
        for (int nt = 0; nt < 4; nt++) {
            int col = warpn * 32 + nt * 8 + 2 * q;
            float* op0 = O + ((size_t)(b * S_ + s0) * QH_ + qh) * HD_ + col;
            float* op1 = O + ((size_t)(b * S_ + s0 + 8) * QH_ + qh) * HD_ + col;
            *(float2*)op0 = make_float2(o[mt][nt][0] * inv0, o[mt][nt][1] * inv0);
            *(float2*)op1 = make_float2(o[mt][nt][2] * inv1, o[mt][nt][3] * inv1);
        }
    }
}

// ---------------------------------------------------------------------------
// Launch
// ---------------------------------------------------------------------------
extern "C" void kernel_launch(void* const* d_in, const int* in_sizes, int n_in,
                              void* d_out, int out_size) {
    const float* x         = (const float*)d_in[0];
    const int*   positions = (const int*)d_in[1];
    const float* Wq        = (const float*)d_in[2];
    const float* Wk        = (const float*)d_in[3];
    const float* Wv        = (const float*)d_in[4];
    const float* Wo        = (const float*)d_in[5];
    float* out = (float*)d_out;

    float *q, *k, *v, *att;
    cudaGetSymbolAddress((void**)&q,   g_q);
    cudaGetSymbolAddress((void**)&k,   g_k);
    cudaGetSymbolAddress((void**)&v,   g_v);
    cudaGetSymbolAddress((void**)&att, g_att);

    // Projections on tensor cores (TF32)
    gemm_tf32<true><<<dim3(QH_, M_ROWS / 128), 256>>>(x, Wq, q, M_ROWS, QH_ * HD_, D_);
    gemm_tf32<true><<<dim3(KH_, M_ROWS / 128), 256>>>(x, Wk, k, M_ROWS, KH_ * HD_, D_);
    gemm_tf32<true><<<dim3(KH_, M_ROWS / 128), 256>>>(x, Wv, v, M_ROWS, KH_ * HD_, D_);

    // RoPE
    {
        int tq = B_ * S_ * QH_ * (HD_ / 2);
        int tk = B_ * S_ * KH_ * (HD_ / 2);
        rope_kernel<<<(tq + 255) / 256, 256>>>(q, positions, QH_, tq);
        rope_kernel<<<(tk + 255) / 256, 256>>>(k, positions, KH_, tk);
    }

    // Flash attention on tensor cores (TF32)
    cudaFuncSetAttribute(flash_tc, cudaFuncAttributeMaxDynamicSharedMemorySize,
                         FLASH_SMEM);
    flash_tc<<<dim3(S_ / 64, B_ * QH_), 256, FLASH_SMEM>>>(q, k, v, att);

    // Output projection on tensor cores (Wo flat is [QH*HD, D] row-major)
    gemm_tf32<false><<<dim3(D_ / 128, M_ROWS / 128), 256>>>(att, Wo, out, M_ROWS, D_,
                                                            QH_ * HD_);
}

// round 5
// speedup vs baseline: 3.5168x; 1.0233x over previous
#include <cuda_runtime.h>
#include <math.h>
#include <stdint.h>

// Problem dimensions (fixed by the dataset)
#define B_  2
#define S_  2048
#define D_  2048
#define QH_ 16
#define KH_ 4
#define HD_ 128
#define M_ROWS (B_ * S_)   // 4096

// ---------------------------------------------------------------------------
// Scratch (no allocations allowed -> __device__ globals)
// ---------------------------------------------------------------------------
__device__ float g_q[B_ * S_ * QH_ * HD_];   // 8M floats
__device__ float g_k[B_ * S_ * KH_ * HD_];   // 2M
__device__ float g_v[B_ * S_ * KH_ * HD_];   // 2M
__device__ float g_att[B_ * S_ * QH_ * HD_]; // 8M

// ---------------------------------------------------------------------------
// TF32 / cp.async helpers
// ---------------------------------------------------------------------------
__device__ __forceinline__ uint32_t f2tf32(float f) {
    uint32_t u;
    asm("cvt.rna.tf32.f32 %0, %1;" : "=r"(u) : "f"(f));
    return u;
}

__device__ __forceinline__ void mma_tf32(float* c, const uint32_t* a, const uint32_t* b) {
    asm volatile(
        "mma.sync.aligned.m16n8k8.row.col.f32.tf32.tf32.f32 "
        "{%0,%1,%2,%3}, {%4,%5,%6,%7}, {%8,%9}, {%0,%1,%2,%3};\n"
        : "+f"(c[0]), "+f"(c[1]), "+f"(c[2]), "+f"(c[3])
        : "r"(a[0]), "r"(a[1]), "r"(a[2]), "r"(a[3]), "r"(b[0]), "r"(b[1]));
}

__device__ __forceinline__ void cp_async16(void* sptr, const void* gptr) {
    uint32_t sa = (uint32_t)__cvta_generic_to_shared(sptr);
    asm volatile("cp.async.cg.shared.global [%0], [%1], 16;\n" :: "r"(sa), "l"(gptr));
}
#define CP_COMMIT() asm volatile("cp.async.commit_group;\n" ::: "memory")
#define CP_WAIT1()  asm volatile("cp.async.wait_group 1;\n" ::: "memory")

// ---------------------------------------------------------------------------
// Pipelined TF32 GEMM body. 128x128 block tile, BK=32, 3-stage cp.async.
// 256 threads = 8 warps (2m x 4n), warp tile 64x32, m16n8k8.
// Smem (floats): As[m][k] stride 36, Bs[k][n] stride 136 (conflict-free).
//   A tile: rows brow..brow+127 of A[*, K]
//   W tile: Wp[k * wld + c], c in 0..127  (Wp pre-offset to this column block)
//   C: C[(brow+r) * ldc + ccol + c]
// ---------------------------------------------------------------------------
#define GSTAGES 3
#define ASTG (128 * 36)
#define BSTG (32 * 136)
#define STG_WORDS (ASTG + BSTG)
#define GEMM_SMEM (GSTAGES * STG_WORDS * 4)

__device__ __forceinline__ void gemm_body(const float* __restrict__ A,
                                          const float* __restrict__ Wp,
                                          float* __restrict__ C,
                                          int K, int ldc, int wld,
                                          int brow, int ccol, float* smem) {
    const int tid  = threadIdx.x;
    const int lane = tid & 31;
    const int wid  = tid >> 5;
    const int warpm = wid >> 2;
    const int warpn = wid & 3;
    const int g = lane >> 2;
    const int q = lane & 3;

    const int am  = tid >> 3;          // 0..31
    const int ak4 = (tid & 7) << 2;    // 0..28
    const int bk  = tid >> 5;          // 0..7
    const int bn4 = (tid & 31) << 2;   // 0..124

    const int NITER = K >> 5;

    const float* Abase = A + (size_t)(brow + am) * K + ak4;

    float acc[4][4][4];
#pragma unroll
    for (int mt = 0; mt < 4; mt++)
#pragma unroll
        for (int nt = 0; nt < 4; nt++)
#pragma unroll
            for (int i = 0; i < 4; i++) acc[mt][nt][i] = 0.f;

    // --- tile issue (cp.async, 8 x 16B per thread) ---
    auto issue_tile = [&](int t) {
        float* As = smem + (t % GSTAGES) * STG_WORDS;
        float* Bs = As + ASTG;
        const int k0 = t << 5;
        const float* ap = Abase + k0;
#pragma unroll
        for (int p = 0; p < 4; p++)
            cp_async16(As + (am + 32 * p) * 36 + ak4, ap + (size_t)(32 * p) * K);
        const float* wp = Wp + (size_t)(k0 + bk) * wld + bn4;
#pragma unroll
        for (int p = 0; p < 4; p++)
            cp_async16(Bs + (bk + 8 * p) * 136 + bn4, wp + (size_t)(8 * p) * wld);
    };

    issue_tile(0); CP_COMMIT();
    issue_tile(1); CP_COMMIT();

    for (int i = 0; i < NITER; i++) {
        CP_WAIT1();
        __syncthreads();
        if (i + 2 < NITER) issue_tile(i + 2);
        CP_COMMIT();

        const float* As = smem + (i % GSTAGES) * STG_WORDS;
        const float* Bs = As + ASTG;

#pragma unroll
        for (int kk = 0; kk < 4; kk++) {
            const int kc = kk * 8;
            uint32_t af[4][4];
            uint32_t bf[4][2];
#pragma unroll
            for (int mt = 0; mt < 4; mt++) {
                int r = warpm * 64 + mt * 16 + g;
                af[mt][0] = f2tf32(As[r * 36 + kc + q]);
                af[mt][1] = f2tf32(As[(r + 8) * 36 + kc + q]);
                af[mt][2] = f2tf32(As[r * 36 + kc + q + 4]);
                af[mt][3] = f2tf32(As[(r + 8) * 36 + kc + q + 4]);
            }
#pragma unroll
            for (int nt = 0; nt < 4; nt++) {
                int c = warpn * 32 + nt * 8 + g;
                bf[nt][0] = f2tf32(Bs[(kc + q) * 136 + c]);
                bf[nt][1] = f2tf32(Bs[(kc + q + 4) * 136 + c]);
            }
#pragma unroll
            for (int mt = 0; mt < 4; mt++)
#pragma unroll
                for (int nt = 0; nt < 4; nt++)
                    mma_tf32(acc[mt][nt], af[mt], bf[nt]);
        }
    }

    // ---- epilogue ----
#pragma unroll
    for (int mt = 0; mt < 4; mt++) {
        int r = brow + warpm * 64 + mt * 16 + g;
#pragma unroll
        for (int nt = 0; nt < 4; nt++) {
            int c = ccol + warpn * 32 + nt * 8 + 2 * q;
            *(float2*)&C[(size_t)r * ldc + c] = make_float2(acc[mt][nt][0], acc[mt][nt][1]);
            *(float2*)&C[(size_t)(r + 8) * ldc + c] = make_float2(acc[mt][nt][2], acc[mt][nt][3]);
        }
    }
}

// Merged QKV projection: grid (24 head-blocks, 32 row-blocks)
__global__ __launch_bounds__(256) void qkv_proj(const float* __restrict__ x,
                                                const float* __restrict__ Wq,
                                                const float* __restrict__ Wk,
                                                const float* __restrict__ Wv,
                                                float* __restrict__ qo,
                                                float* __restrict__ ko,
                                                float* __restrict__ vo) {
    extern __shared__ float sm_f[];
    const int h = blockIdx.x;
    const int brow = blockIdx.y * 128;
    if (h < QH_) {
        gemm_body(x, Wq + (size_t)h * D_ * HD_, qo, D_, QH_ * HD_, HD_, brow, h * HD_, sm_f);
    } else if (h < QH_ + KH_) {
        int hh = h - QH_;
        gemm_body(x, Wk + (size_t)hh * D_ * HD_, ko, D_, KH_ * HD_, HD_, brow, hh * HD_, sm_f);
    } else {
        int hh = h - QH_ - KH_;
        gemm_body(x, Wv + (size_t)hh * D_ * HD_, vo, D_, KH_ * HD_, HD_, brow, hh * HD_, sm_f);
    }
}

// Output projection: grid (16 col-blocks, 32 row-blocks)
__global__ __launch_bounds__(256) void o_proj(const float* __restrict__ att,
                                              const float* __restrict__ Wo,
                                              float* __restrict__ out) {
    extern __shared__ float sm_f[];
    const int bcol = blockIdx.x * 128;
    const int brow = blockIdx.y * 128;
    gemm_body(att, Wo + bcol, out, QH_ * HD_, D_, D_, brow, bcol, sm_f);
}

// ---------------------------------------------------------------------------
// RoPE (in-place) on [B, S, NH, 128]
// ---------------------------------------------------------------------------
__global__ void rope_kernel(float* __restrict__ x, const int* __restrict__ positions,
                            int NH, int total) {
    int i = blockIdx.x * blockDim.x + threadIdx.x;
    if (i >= total) return;
    int hp = i & 63;
    int rest = i >> 6;
    int nh = rest % NH;
    int s  = (rest / NH) % S_;
    int b  = rest / (NH * S_);

    float pos = (float)positions[s];
    float ts  = expf(((float)hp / 64.f) * 9.21034037197618f /* ln(1e4) */);
    float ang = pos / ts;
    float sn = sinf(ang);
    float cs = cosf(ang);

    size_t base = ((size_t)(b * S_ + s) * NH + nh) * HD_;
    float x1 = x[base + hp];
    float x2 = x[base + hp + 64];
    x[base + hp]      = x1 * cs - x2 * sn;
    x[base + hp + 64] = x2 * cs + x1 * sn;
}

// ---------------------------------------------------------------------------
// Flash attention, TF32 tensor cores (causal, GQA) — unchanged from R3.
// ---------------------------------------------------------------------------
#define FQS 132
#define FKS 132
#define FVS 136
#define FPS 68

#define FLASH_SMEM ((64 * FQS + 64 * FKS + 64 * FVS + 64 * FPS + 2 * 256 + 2 * 64) * 4)

__global__ __launch_bounds__(256) void flash_tc(const float* __restrict__ Q,
                                                const float* __restrict__ K,
                                                const float* __restrict__ V,
                                                float* __restrict__ O) {
    extern __shared__ uint32_t sm_u[];
    uint32_t* Qs = sm_u;                 // [64][132]
    uint32_t* Ks = Qs + 64 * FQS;        // [64][132]
    uint32_t* Vs = Ks + 64 * FKS;        // [64][136]
    uint32_t* Ps = Vs + 64 * FVS;        // [64][68]
    float* smax  = (float*)(Ps + 64 * FPS);  // [4][64]
    float* ssum  = smax + 256;               // [4][64]
    float* rm    = ssum + 256;               // [64]
    float* rl    = rm + 64;                  // [64]

    const int tid  = threadIdx.x;
    const int lane = tid & 31;
    const int wid  = tid >> 5;
    const int warpm = wid >> 2;
    const int warpn = wid & 3;
    const int g = lane >> 2;
    const int q = lane & 3;

    const int mblk = gridDim.x - 1 - blockIdx.x;
    const int bq = blockIdx.y;
    const int b  = bq / QH_;
    const int qh = bq % QH_;
    const int kvh = qh / (QH_ / KH_);

    for (int idx = tid; idx < 64 * 32; idx += 256) {
        int r  = idx >> 5;
        int c4 = (idx & 31) << 2;
        float4 v4 = *(const float4*)(Q + ((size_t)(b * S_ + mblk * 64 + r) * QH_ + qh) * HD_ + c4);
        uint4 t = make_uint4(f2tf32(v4.x), f2tf32(v4.y), f2tf32(v4.z), f2tf32(v4.w));
        *(uint4*)&Qs[r * FQS + c4] = t;
    }
    if (tid < 64) { rm[tid] = -INFINITY; rl[tid] = 0.f; }

    float o[2][4][4];
#pragma unroll
    for (int mt = 0; mt < 2; mt++)
#pragma unroll
        for (int nt = 0; nt < 4; nt++)
#pragma unroll
            for (int i = 0; i < 4; i++) o[mt][nt][i] = 0.f;

    const float scale = 0.08838834764831845f;  // 1/sqrt(128)
    const int row_base = warpm * 32 + g;
    const int qkcol_base = warpn * 16 + 2 * q;

    for (int n = 0; n <= mblk; n++) {
        __syncthreads();

        for (int idx = tid; idx < 64 * 32; idx += 256) {
            int r  = idx >> 5;
            int c4 = (idx & 31) << 2;
            float4 kv = *(const float4*)(K + ((size_t)(b * S_ + n * 64 + r) * KH_ + kvh) * HD_ + c4);
            uint4 t = make_uint4(f2tf32(kv.x), f2tf32(kv.y), f2tf32(kv.z), f2tf32(kv.w));
            *(uint4*)&Ks[r * FKS + c4] = t;
        }
        for (int idx = tid; idx < 64 * 32; idx += 256) {
            int r  = idx >> 5;
            int c4 = (idx & 31) << 2;
            float4 vv = *(const float4*)(V + ((size_t)(b * S_ + n * 64 + r) * KH_ + kvh) * HD_ + c4);
            uint4 t = make_uint4(f2tf32(vv.x), f2tf32(vv.y), f2tf32(vv.z), f2tf32(vv.w));
            *(uint4*)&Vs[r * FVS + c4] = t;
        }
        __syncthreads();

        float s[2][2][4];
#pragma unroll
        for (int mt = 0; mt < 2; mt++)
#pragma unroll
            for (int nt = 0; nt < 2; nt++)
#pragma unroll
                for (int i = 0; i < 4; i++) s[mt][nt][i] = 0.f;

#pragma unroll
        for (int ks = 0; ks < 16; ks++) {
            const int kc = ks * 8;
            uint32_t af[2][4], bf[2][2];
#pragma unroll
            for (int mt = 0; mt < 2; mt++) {
                int r = warpm * 32 + mt * 16 + g;
                af[mt][0] = Qs[r * FQS + kc + q];
                af[mt][1] = Qs[(r + 8) * FQS + kc + q];
                af[mt][2] = Qs[r * FQS + kc + q + 4];
                af[mt][3] = Qs[(r + 8) * FQS + kc + q + 4];
            }
#pragma unroll
            for (int nt = 0; nt < 2; nt++) {
                int c = warpn * 16 + nt * 8 + g;
                bf[nt][0] = Ks[c * FKS + kc + q];
                bf[nt][1] = Ks[c * FKS + kc + q + 4];
            }
#pragma unroll
            for (int mt = 0; mt < 2; mt++)
#pragma unroll
                for (int nt = 0; nt < 2; nt++)
                    mma_tf32(s[mt][nt], af[mt], bf[nt]);
        }

        const int gr_base = mblk * 64 + row_base;
        const int gc_base = n * 64 + qkcol_base;
#pragma unroll
        for (int mt = 0; mt < 2; mt++) {
            int gr0 = gr_base + mt * 16;
            int gr1 = gr0 + 8;
#pragma unroll
            for (int nt = 0; nt < 2; nt++) {
                int gc0 = gc_base + nt * 8;
                int gc1 = gc0 + 1;
                s[mt][nt][0] = (gc0 > gr0) ? -1e9f : s[mt][nt][0] * scale;
                s[mt][nt][1] = (gc1 > gr0) ? -1e9f : s[mt][nt][1] * scale;
                s[mt][nt][2] = (gc0 > gr1) ? -1e9f : s[mt][nt][2] * scale;
                s[mt][nt][3] = (gc1 > gr1) ? -1e9f : s[mt][nt][3] * scale;
            }
        }

#pragma unroll
        for (int mt = 0; mt < 2; mt++)
#pragma unroll
            for (int h = 0; h < 2; h++) {
                float pm = fmaxf(fmaxf(s[mt][0][2 * h], s[mt][0][2 * h + 1]),
                                 fmaxf(s[mt][1][2 * h], s[mt][1][2 * h + 1]));
                pm = fmaxf(pm, __shfl_xor_sync(0xFFFFFFFF, pm, 1));
                pm = fmaxf(pm, __shfl_xor_sync(0xFFFFFFFF, pm, 2));
                if (q == 0) smax[warpn * 64 + row_base + mt * 16 + 8 * h] = pm;
            }
        __syncthreads();

        float corr[2][2];
#pragma unroll
        for (int mt = 0; mt < 2; mt++)
#pragma unroll
            for (int h = 0; h < 2; h++) {
                int row = row_base + mt * 16 + 8 * h;
                float m_tile = fmaxf(fmaxf(smax[row], smax[64 + row]),
                                     fmaxf(smax[128 + row], smax[192 + row]));
                float m_old = rm[row];
                float m_new = fmaxf(m_old, m_tile);
                corr[mt][h] = __expf(m_old - m_new);

                float psum = 0.f;
#pragma unroll
                for (int nt = 0; nt < 2; nt++) {
                    float p0 = __expf(s[mt][nt][2 * h] - m_new);
                    float p1 = __expf(s[mt][nt][2 * h + 1] - m_new);
                    psum += p0 + p1;
                    int col = qkcol_base + nt * 8;
                    *(uint2*)&Ps[row * FPS + col] = make_uint2(f2tf32(p0), f2tf32(p1));
                }
                psum += __shfl_xor_sync(0xFFFFFFFF, psum, 1);
                psum += __shfl_xor_sync(0xFFFFFFFF, psum, 2);
                if (q == 0) ssum[warpn * 64 + row] = psum;
                if (warpn == 0 && q == 0) rm[row] = m_new;
            }
        __syncthreads();

        if (warpn == 0 && q == 0) {
#pragma unroll
            for (int mt = 0; mt < 2; mt++)
#pragma unroll
                for (int h = 0; h < 2; h++) {
                    int row = row_base + mt * 16 + 8 * h;
                    float ts = ssum[row] + ssum[64 + row] + ssum[128 + row] + ssum[192 + row];
                    rl[row] = rl[row] * corr[mt][h] + ts;
                }
        }

#pragma unroll
        for (int mt = 0; mt < 2; mt++)
#pragma unroll
            for (int nt = 0; nt < 4; nt++) {
                o[mt][nt][0] *= corr[mt][0];
                o[mt][nt][1] *= corr[mt][0];
                o[mt][nt][2] *= corr[mt][1];
                o[mt][nt][3] *= corr[mt][1];
            }

#pragma unroll
        for (int ks = 0; ks < 8; ks++) {
            const int kc = ks * 8;
            uint32_t af[2][4], bf[4][2];
#pragma unroll
            for (int mt = 0; mt < 2; mt++) {
                int r = warpm * 32 + mt * 16 + g;
                af[mt][0] = Ps[r * FPS + kc + q];
                af[mt][1] = Ps[(r + 8) * FPS + kc + q];
                af[mt][2] = Ps[r * FPS + kc + q + 4];
                af[mt][3] = Ps[(r + 8) * FPS + kc + q + 4];
            }
#pragma unroll
            for (int nt = 0; nt < 4; nt++) {
                int c = warpn * 32 + nt * 8 + g;
                bf[nt][0] = Vs[(kc + q) * FVS + c];
                bf[nt][1] = Vs[(kc + q + 4) * FVS + c];
            }
#pragma unroll
            for (int mt = 0; mt < 2; mt++)
#pragma unroll
                for (int nt = 0; nt < 4; nt++)
                    mma_tf32(o[mt][nt], af[mt], bf[nt]);
        }
    }

#pragma unroll
    for (int mt = 0; mt < 2; mt++) {
        float inv0 = 1.0f / rl[row_base + mt * 16];
        float inv1 = 1.0f / rl[row_base + mt * 16 + 8];
        int s0 = mblk * 64 + row_base + mt * 16;
#pragma unroll
        for (int nt = 0; nt < 4; nt++) {
            int col = warpn * 32 + nt * 8 + 2 * q;
            float* op0 = O + ((size_t)(b * S_ + s0) * QH_ + qh) * HD_ + col;
            float* op1 = O + ((size_t)(b * S_ + s0 + 8) * QH_ + qh) * HD_ + col;
            *(float2*)op0 = make_float2(o[mt][nt][0] * inv0, o[mt][nt][1] * inv0);
            *(float2*)op1 = make_float2(o[mt][nt][2] * inv1, o[mt][nt][3] * inv1);
        }
    }
}

// ---------------------------------------------------------------------------
// Launch
// ---------------------------------------------------------------------------
extern "C" void kernel_launch(void* const* d_in, const int* in_sizes, int n_in,
                              void* d_out, int out_size) {
    const float* x         = (const float*)d_in[0];
    const int*   positions = (const int*)d_in[1];
    const float* Wq        = (const float*)d_in[2];
    const float* Wk        = (const float*)d_in[3];
    const float* Wv        = (const float*)d_in[4];
    const float* Wo        = (const float*)d_in[5];
    float* out = (float*)d_out;

    float *q, *k, *v, *att;
    cudaGetSymbolAddress((void**)&q,   g_q);
    cudaGetSymbolAddress((void**)&k,   g_k);
    cudaGetSymbolAddress((void**)&v,   g_v);
    cudaGetSymbolAddress((void**)&att, g_att);

    cudaFuncSetAttribute(qkv_proj, cudaFuncAttributeMaxDynamicSharedMemorySize, GEMM_SMEM);
    cudaFuncSetAttribute(o_proj,   cudaFuncAttributeMaxDynamicSharedMemorySize, GEMM_SMEM);

    // Merged QKV projection (one wave)
    qkv_proj<<<dim3(QH_ + 2 * KH_, M_ROWS / 128), 256, GEMM_SMEM>>>(x, Wq, Wk, Wv, q, k, v);

    // RoPE
    {
        int tq = B_ * S_ * QH_ * (HD_ / 2);
        int tk = B_ * S_ * KH_ * (HD_ / 2);
        rope_kernel<<<(tq + 255) / 256, 256>>>(q, positions, QH_, tq);
        rope_kernel<<<(tk + 255) / 256, 256>>>(k, positions, KH_, tk);
    }

    // Flash attention on tensor cores (TF32)
    cudaFuncSetAttribute(flash_tc, cudaFuncAttributeMaxDynamicSharedMemorySize,
                         FLASH_SMEM);
    flash_tc<<<dim3(S_ / 64, B_ * QH_), 256, FLASH_SMEM>>>(q, k, v, att);

    // Output projection
    o_proj<<<dim3(D_ / 128, M_ROWS / 128), 256, GEMM_SMEM>>>(att, Wo, out);
}

// round 7
// speedup vs baseline: 3.8903x; 1.1062x over previous
#include <cuda_runtime.h>
#include <math.h>
#include <stdint.h>

// Problem dimensions (fixed by the dataset)
#define B_  2
#define S_  2048
#define D_  2048
#define QH_ 16
#define KH_ 4
#define HD_ 128
#define M_ROWS (B_ * S_)   // 4096

// ---------------------------------------------------------------------------
// Scratch (no allocations allowed -> __device__ globals)
// ---------------------------------------------------------------------------
__device__ float g_q[B_ * S_ * QH_ * HD_];   // 8M floats
__device__ float g_k[B_ * S_ * KH_ * HD_];   // 2M
__device__ float g_v[B_ * S_ * KH_ * HD_];   // 2M
__device__ float g_att[B_ * S_ * QH_ * HD_]; // 8M

// ---------------------------------------------------------------------------
// TF32 / cp.async helpers
// ---------------------------------------------------------------------------
__device__ __forceinline__ uint32_t f2tf32(float f) {
    uint32_t u;
    asm("cvt.rna.tf32.f32 %0, %1;" : "=r"(u) : "f"(f));
    return u;
}

__device__ __forceinline__ void mma_tf32(float* c, const uint32_t* a, const uint32_t* b) {
    asm volatile(
        "mma.sync.aligned.m16n8k8.row.col.f32.tf32.tf32.f32 "
        "{%0,%1,%2,%3}, {%4,%5,%6,%7}, {%8,%9}, {%0,%1,%2,%3};\n"
        : "+f"(c[0]), "+f"(c[1]), "+f"(c[2]), "+f"(c[3])
        : "r"(a[0]), "r"(a[1]), "r"(a[2]), "r"(a[3]), "r"(b[0]), "r"(b[1]));
}

__device__ __forceinline__ void cp_async16(void* sptr, const void* gptr) {
    uint32_t sa = (uint32_t)__cvta_generic_to_shared(sptr);
    asm volatile("cp.async.cg.shared.global [%0], [%1], 16;\n" :: "r"(sa), "l"(gptr));
}
#define CP_COMMIT() asm volatile("cp.async.commit_group;\n" ::: "memory")
#define CP_WAIT1()  asm volatile("cp.async.wait_group 1;\n" ::: "memory")

// ---------------------------------------------------------------------------
// Pipelined TF32 GEMM body (unchanged). 128x128 tile, BK=32, 3-stage.
// ---------------------------------------------------------------------------
#define GSTAGES 3
#define ASTG (128 * 36)
#define BSTG (32 * 136)
#define STG_WORDS (ASTG + BSTG)
#define GEMM_SMEM (GSTAGES * STG_WORDS * 4)

__device__ __forceinline__ void gemm_body(const float* __restrict__ A,
                                          const float* __restrict__ Wp,
                                          float* __restrict__ C,
                                          int K, int ldc, int wld,
                                          int brow, int ccol, float* smem) {
    const int tid  = threadIdx.x;
    const int lane = tid & 31;
    const int wid  = tid >> 5;
    const int warpm = wid >> 2;
    const int warpn = wid & 3;
    const int g = lane >> 2;
    const int q = lane & 3;

    const int am  = tid >> 3;
    const int ak4 = (tid & 7) << 2;
    const int bk  = tid >> 5;
    const int bn4 = (tid & 31) << 2;

    const int NITER = K >> 5;

    const float* Abase = A + (size_t)(brow + am) * K + ak4;

    float acc[4][4][4];
#pragma unroll
    for (int mt = 0; mt < 4; mt++)
#pragma unroll
        for (int nt = 0; nt < 4; nt++)
#pragma unroll
            for (int i = 0; i < 4; i++) acc[mt][nt][i] = 0.f;

    auto issue_tile = [&](int t) {
        float* As = smem + (t % GSTAGES) * STG_WORDS;
        float* Bs = As + ASTG;
        const int k0 = t << 5;
        const float* ap = Abase + k0;
#pragma unroll
        for (int p = 0; p < 4; p++)
            cp_async16(As + (am + 32 * p) * 36 + ak4, ap + (size_t)(32 * p) * K);
        const float* wp = Wp + (size_t)(k0 + bk) * wld + bn4;
#pragma unroll
        for (int p = 0; p < 4; p++)
            cp_async16(Bs + (bk + 8 * p) * 136 + bn4, wp + (size_t)(8 * p) * wld);
    };

    issue_tile(0); CP_COMMIT();
    issue_tile(1); CP_COMMIT();

    for (int i = 0; i < NITER; i++) {
        CP_WAIT1();
        __syncthreads();
        if (i + 2 < NITER) issue_tile(i + 2);
        CP_COMMIT();

        const float* As = smem + (i % GSTAGES) * STG_WORDS;
        const float* Bs = As + ASTG;

#pragma unroll
        for (int kk = 0; kk < 4; kk++) {
            const int kc = kk * 8;
            uint32_t af[4][4];
            uint32_t bf[4][2];
#pragma unroll
            for (int mt = 0; mt < 4; mt++) {
                int r = warpm * 64 + mt * 16 + g;
                af[mt][0] = f2tf32(As[r * 36 + kc + q]);
                af[mt][1] = f2tf32(As[(r + 8) * 36 + kc + q]);
                af[mt][2] = f2tf32(As[r * 36 + kc + q + 4]);
                af[mt][3] = f2tf32(As[(r + 8) * 36 + kc + q + 4]);
            }
#pragma unroll
            for (int nt = 0; nt < 4; nt++) {
                int c = warpn * 32 + nt * 8 + g;
                bf[nt][0] = f2tf32(Bs[(kc + q) * 136 + c]);
                bf[nt][1] = f2tf32(Bs[(kc + q + 4) * 136 + c]);
            }
#pragma unroll
            for (int mt = 0; mt < 4; mt++)
#pragma unroll
                for (int nt = 0; nt < 4; nt++)
                    mma_tf32(acc[mt][nt], af[mt], bf[nt]);
        }
    }

#pragma unroll
    for (int mt = 0; mt < 4; mt++) {
        int r = brow + warpm * 64 + mt * 16 + g;
#pragma unroll
        for (int nt = 0; nt < 4; nt++) {
            int c = ccol + warpn * 32 + nt * 8 + 2 * q;
            *(float2*)&C[(size_t)r * ldc + c] = make_float2(acc[mt][nt][0], acc[mt][nt][1]);
            *(float2*)&C[(size_t)(r + 8) * ldc + c] = make_float2(acc[mt][nt][2], acc[mt][nt][3]);
        }
    }
}

// Merged QKV projection: grid (24 head-blocks, 32 row-blocks)
__global__ __launch_bounds__(256) void qkv_proj(const float* __restrict__ x,
                                                const float* __restrict__ Wq,
                                                const float* __restrict__ Wk,
                                                const float* __restrict__ Wv,
                                                float* __restrict__ qo,
                                                float* __restrict__ ko,
                                                float* __restrict__ vo) {
    extern __shared__ float sm_f[];
    const int h = blockIdx.x;
    const int brow = blockIdx.y * 128;
    if (h < QH_) {
        gemm_body(x, Wq + (size_t)h * D_ * HD_, qo, D_, QH_ * HD_, HD_, brow, h * HD_, sm_f);
    } else if (h < QH_ + KH_) {
        int hh = h - QH_;
        gemm_body(x, Wk + (size_t)hh * D_ * HD_, ko, D_, KH_ * HD_, HD_, brow, hh * HD_, sm_f);
    } else {
        int hh = h - QH_ - KH_;
        gemm_body(x, Wv + (size_t)hh * D_ * HD_, vo, D_, KH_ * HD_, HD_, brow, hh * HD_, sm_f);
    }
}

// Output projection: grid (16 col-blocks, 32 row-blocks)
__global__ __launch_bounds__(256) void o_proj(const float* __restrict__ att,
                                              const float* __restrict__ Wo,
                                              float* __restrict__ out) {
    extern __shared__ float sm_f[];
    const int bcol = blockIdx.x * 128;
    const int brow = blockIdx.y * 128;
    gemm_body(att, Wo + bcol, out, QH_ * HD_, D_, D_, brow, bcol, sm_f);
}

// ---------------------------------------------------------------------------
// RoPE (in-place) on [B, S, NH, 128]. Writes tf32-rounded values.
// ---------------------------------------------------------------------------
__global__ void rope_kernel(float* __restrict__ x, const int* __restrict__ positions,
                            int NH, int total) {
    int i = blockIdx.x * blockDim.x + threadIdx.x;
    if (i >= total) return;
    int hp = i & 63;
    int rest = i >> 6;
    int nh = rest % NH;
    int s  = (rest / NH) % S_;
    int b  = rest / (NH * S_);

    float pos = (float)positions[s];
    float ts  = expf(((float)hp / 64.f) * 9.21034037197618f /* ln(1e4) */);
    float ang = pos / ts;
    float sn = sinf(ang);
    float cs = cosf(ang);

    size_t base = ((size_t)(b * S_ + s) * NH + nh) * HD_;
    float x1 = x[base + hp];
    float x2 = x[base + hp + 64];
    x[base + hp]      = __uint_as_float(f2tf32(x1 * cs - x2 * sn));
    x[base + hp + 64] = __uint_as_float(f2tf32(x2 * cs + x1 * sn));
}

// ---------------------------------------------------------------------------
// Flash attention v2b: TF32 tensor cores, causal, GQA.
// 128-query tiles, 512 threads = 16 warps (4m x 4n).
// Softmax row state (m, l) is REGISTER-RESIDENT per warp (all warps compute
// identical values from shared smax/ssum; no shared read-write race).
// cp.async: double-buffered K, prefetched V. Pair-interleaved Q/P layouts.
// ---------------------------------------------------------------------------
#define QS2 136
#define KS2 132
#define VS2 136
#define PS2 72
#define KTILE_W (64 * KS2)

#define F2_SMEM ((128 * QS2 + 2 * KTILE_W + 64 * VS2 + 128 * PS2 + 512 + 512) * 4)

__global__ __launch_bounds__(512) void flash_tc2(const float* __restrict__ Q,
                                                 const float* __restrict__ K,
                                                 const float* __restrict__ V,
                                                 float* __restrict__ O) {
    extern __shared__ uint32_t sm_u[];
    uint32_t* Qs = sm_u;                    // [128][136] pair layout
    uint32_t* Kb = Qs + 128 * QS2;          // 2 x [64][132] natural
    uint32_t* Vs = Kb + 2 * KTILE_W;        // [64][136] natural
    uint32_t* Ps = Vs + 64 * VS2;           // [128][72] pair layout
    float* smax  = (float*)(Ps + 128 * PS2);   // [4][128]
    float* ssum  = smax + 512;                 // [4][128]

    const int tid  = threadIdx.x;
    const int lane = tid & 31;
    const int wid  = tid >> 5;
    const int warpm = wid >> 2;   // 0..3
    const int warpn = wid & 3;    // 0..3
    const int g = lane >> 2;      // 0..7
    const int q = lane & 3;       // 0..3

    const int mblk = gridDim.x - 1 - blockIdx.x;   // heavy tiles first
    const int bq = blockIdx.y;
    const int b  = bq / QH_;
    const int qh = bq % QH_;
    const int kvh = qh / (QH_ / KH_);

    // ---- load Q tile [128][128] into pair layout (already tf32-rounded) ----
    for (int idx = tid; idx < 128 * 32; idx += 512) {
        int r  = idx >> 5;
        int c4 = (idx & 31) << 2;
        float4 v4 = *(const float4*)(Q + ((size_t)(b * S_ + mblk * 128 + r) * QH_ + qh) * HD_ + c4);
        uint32_t* dst = Qs + r * QS2 + ((c4 >> 3) << 3) + ((c4 >> 2) & 1);
        dst[0] = __float_as_uint(v4.x);
        dst[2] = __float_as_uint(v4.y);
        dst[4] = __float_as_uint(v4.z);
        dst[6] = __float_as_uint(v4.w);
    }

    // Register-resident softmax state, replicated across warpn (consistent by
    // construction: updated only from shared smax/ssum all warps read alike).
    float rmr[2][2], rlr[2][2];
#pragma unroll
    for (int mt = 0; mt < 2; mt++)
#pragma unroll
        for (int h = 0; h < 2; h++) { rmr[mt][h] = -INFINITY; rlr[mt][h] = 0.f; }

    float o[2][4][4];
#pragma unroll
    for (int mt = 0; mt < 2; mt++)
#pragma unroll
        for (int nt = 0; nt < 4; nt++)
#pragma unroll
            for (int i = 0; i < 4; i++) o[mt][nt][i] = 0.f;

    const float scale = 0.08838834764831845f;  // 1/sqrt(128)
    const int row_base = warpm * 32 + g;       // + mt*16 (+8h)
    const int qkcol_base = warpn * 16 + 2 * q; // + nt*8 (+1)
    const int NIT = 2 * mblk + 2;

    auto issueK = [&](int n) {
        uint32_t* kd = Kb + (n & 1) * KTILE_W;
        for (int idx = tid; idx < 64 * 32; idx += 512) {
            int r  = idx >> 5;
            int c4 = (idx & 31) << 2;
            cp_async16(kd + r * KS2 + c4,
                       K + ((size_t)(b * S_ + n * 64 + r) * KH_ + kvh) * HD_ + c4);
        }
    };
    auto issueV = [&](int n) {
        for (int idx = tid; idx < 64 * 32; idx += 512) {
            int r  = idx >> 5;
            int c4 = (idx & 31) << 2;
            cp_async16(Vs + r * VS2 + c4,
                       V + ((size_t)(b * S_ + n * 64 + r) * KH_ + kvh) * HD_ + c4);
        }
    };

    issueK(0); issueV(0); CP_COMMIT();

    for (int n = 0; n < NIT; n++) {
        if (n + 1 < NIT) issueK(n + 1);
        CP_COMMIT();
        CP_WAIT1();
        __syncthreads();           // A: K(n),V(n) ready; Ps/smax/ssum reusable

        const uint32_t* Kst = Kb + (n & 1) * KTILE_W;

        // ---- QK^T ----
        float s[2][2][4];
#pragma unroll
        for (int mt = 0; mt < 2; mt++)
#pragma unroll
            for (int nt = 0; nt < 2; nt++)
#pragma unroll
                for (int i = 0; i < 4; i++) s[mt][nt][i] = 0.f;

#pragma unroll
        for (int ks = 0; ks < 16; ks++) {
            const int kc = ks * 8;
            uint32_t af[2][4], bf[2][2];
#pragma unroll
            for (int mt = 0; mt < 2; mt++) {
                int r = warpm * 32 + mt * 16 + g;
                uint2 a0 = *(const uint2*)&Qs[r * QS2 + kc + q * 2];
                uint2 a1 = *(const uint2*)&Qs[(r + 8) * QS2 + kc + q * 2];
                af[mt][0] = a0.x; af[mt][2] = a0.y;
                af[mt][1] = a1.x; af[mt][3] = a1.y;
            }
#pragma unroll
            for (int nt = 0; nt < 2; nt++) {
                int c = warpn * 16 + nt * 8 + g;
                bf[nt][0] = Kst[c * KS2 + kc + q];       // rope pre-rounded tf32
                bf[nt][1] = Kst[c * KS2 + kc + q + 4];
            }
#pragma unroll
            for (int mt = 0; mt < 2; mt++)
#pragma unroll
                for (int nt = 0; nt < 2; nt++)
                    mma_tf32(s[mt][nt], af[mt], bf[nt]);
        }

        // ---- scale + causal mask ----
        if (n >= 2 * mblk) {
            const int gr_base = mblk * 128 + row_base;
            const int gc_base = n * 64 + qkcol_base;
#pragma unroll
            for (int mt = 0; mt < 2; mt++) {
                int gr0 = gr_base + mt * 16;
                int gr1 = gr0 + 8;
#pragma unroll
                for (int nt = 0; nt < 2; nt++) {
                    int gc0 = gc_base + nt * 8;
                    int gc1 = gc0 + 1;
                    s[mt][nt][0] = (gc0 > gr0) ? -1e9f : s[mt][nt][0] * scale;
                    s[mt][nt][1] = (gc1 > gr0) ? -1e9f : s[mt][nt][1] * scale;
                    s[mt][nt][2] = (gc0 > gr1) ? -1e9f : s[mt][nt][2] * scale;
                    s[mt][nt][3] = (gc1 > gr1) ? -1e9f : s[mt][nt][3] * scale;
                }
            }
        } else {
#pragma unroll
            for (int mt = 0; mt < 2; mt++)
#pragma unroll
                for (int nt = 0; nt < 2; nt++)
#pragma unroll
                    for (int i = 0; i < 4; i++) s[mt][nt][i] *= scale;
        }

        // ---- partial row max -> smax ----
#pragma unroll
        for (int mt = 0; mt < 2; mt++)
#pragma unroll
            for (int h = 0; h < 2; h++) {
                float pm = fmaxf(fmaxf(s[mt][0][2 * h], s[mt][0][2 * h + 1]),
                                 fmaxf(s[mt][1][2 * h], s[mt][1][2 * h + 1]));
                pm = fmaxf(pm, __shfl_xor_sync(0xFFFFFFFF, pm, 1));
                pm = fmaxf(pm, __shfl_xor_sync(0xFFFFFFFF, pm, 2));
                if (q == 0) smax[warpn * 128 + row_base + mt * 16 + 8 * h] = pm;
            }
        __syncthreads();           // B: smax complete

        // ---- m update (registers), exp, P store, partial sums ----
        const int poff0 = (((2 * q) & 3) << 1) + (q >> 1);
        const int poff1 = (((2 * q + 1) & 3) << 1) + ((2 * q + 1) >> 2);
        float corr[2][2];
#pragma unroll
        for (int mt = 0; mt < 2; mt++)
#pragma unroll
            for (int h = 0; h < 2; h++) {
                int row = row_base + mt * 16 + 8 * h;
                float m_tile = fmaxf(fmaxf(smax[row], smax[128 + row]),
                                     fmaxf(smax[256 + row], smax[384 + row]));
                float m_old = rmr[mt][h];
                float m_new = fmaxf(m_old, m_tile);
                corr[mt][h] = __expf(m_old - m_new);
                rmr[mt][h] = m_new;

                float psum = 0.f;
#pragma unroll
                for (int nt = 0; nt < 2; nt++) {
                    float p0 = __expf(s[mt][nt][2 * h] - m_new);
                    float p1 = __expf(s[mt][nt][2 * h + 1] - m_new);
                    psum += p0 + p1;
                    uint32_t* pb = Ps + row * PS2 + (warpn * 2 + nt) * 8;
                    pb[poff0] = f2tf32(p0);
                    pb[poff1] = f2tf32(p1);
                }
                psum += __shfl_xor_sync(0xFFFFFFFF, psum, 1);
                psum += __shfl_xor_sync(0xFFFFFFFF, psum, 2);
                if (q == 0) ssum[warpn * 128 + row] = psum;
            }
        __syncthreads();           // C: Ps + ssum complete

        // ---- l update (registers) ----
#pragma unroll
        for (int mt = 0; mt < 2; mt++)
#pragma unroll
            for (int h = 0; h < 2; h++) {
                int row = row_base + mt * 16 + 8 * h;
                float ts = ssum[row] + ssum[128 + row] + ssum[256 + row] + ssum[384 + row];
                rlr[mt][h] = rlr[mt][h] * corr[mt][h] + ts;
            }

        // ---- rescale O, then PV mma ----
#pragma unroll
        for (int mt = 0; mt < 2; mt++)
#pragma unroll
            for (int nt = 0; nt < 4; nt++) {
                o[mt][nt][0] *= corr[mt][0];
                o[mt][nt][1] *= corr[mt][0];
                o[mt][nt][2] *= corr[mt][1];
                o[mt][nt][3] *= corr[mt][1];
            }

#pragma unroll
        for (int ks = 0; ks < 8; ks++) {
            const int kc = ks * 8;
            uint32_t af[2][4], bf[4][2];
#pragma unroll
            for (int mt = 0; mt < 2; mt++) {
                int r = warpm * 32 + mt * 16 + g;
                uint2 a0 = *(const uint2*)&Ps[r * PS2 + kc + q * 2];
                uint2 a1 = *(const uint2*)&Ps[(r + 8) * PS2 + kc + q * 2];
                af[mt][0] = a0.x; af[mt][2] = a0.y;
                af[mt][1] = a1.x; af[mt][3] = a1.y;
            }
#pragma unroll
            for (int nt = 0; nt < 4; nt++) {
                int c = warpn * 32 + nt * 8 + g;
                bf[nt][0] = f2tf32(__uint_as_float(Vs[(kc + q) * VS2 + c]));
                bf[nt][1] = f2tf32(__uint_as_float(Vs[(kc + q + 4) * VS2 + c]));
            }
#pragma unroll
            for (int mt = 0; mt < 2; mt++)
#pragma unroll
                for (int nt = 0; nt < 4; nt++)
                    mma_tf32(o[mt][nt], af[mt], bf[nt]);
        }

        __syncthreads();           // D: all warps done with Ps/Vs
        if (n + 1 < NIT) issueV(n + 1);
        CP_COMMIT();
    }

    // ---- epilogue ----
#pragma unroll
    for (int mt = 0; mt < 2; mt++) {
        float inv0 = 1.0f / rlr[mt][0];
        float inv1 = 1.0f / rlr[mt][1];
        int s0 = mblk * 128 + row_base + mt * 16;
#pragma unroll
        for (int nt = 0; nt < 4; nt++) {
            int col = warpn * 32 + nt * 8 + 2 * q;
            float* op0 = O + ((size_t)(b * S_ + s0) * QH_ + qh) * HD_ + col;
            float* op1 = O + ((size_t)(b * S_ + s0 + 8) * QH_ + qh) * HD_ + col;
            *(float2*)op0 = make_float2(o[mt][nt][0] * inv0, o[mt][nt][1] * inv0);
            *(float2*)op1 = make_float2(o[mt][nt][2] * inv1, o[mt][nt][3] * inv1);
        }
    }
}

// ---------------------------------------------------------------------------
// Launch
// ---------------------------------------------------------------------------
extern "C" void kernel_launch(void* const* d_in, const int* in_sizes, int n_in,
                              void* d_out, int out_size) {
    const float* x         = (const float*)d_in[0];
    const int*   positions = (const int*)d_in[1];
    const float* Wq        = (const float*)d_in[2];
    const float* Wk        = (const float*)d_in[3];
    const float* Wv        = (const float*)d_in[4];
    const float* Wo        = (const float*)d_in[5];
    float* out = (float*)d_out;

    float *q, *k, *v, *att;
    cudaGetSymbolAddress((void**)&q,   g_q);
    cudaGetSymbolAddress((void**)&k,   g_k);
    cudaGetSymbolAddress((void**)&v,   g_v);
    cudaGetSymbolAddress((void**)&att, g_att);

    cudaFuncSetAttribute(qkv_proj, cudaFuncAttributeMaxDynamicSharedMemorySize, GEMM_SMEM);
    cudaFuncSetAttribute(o_proj,   cudaFuncAttributeMaxDynamicSharedMemorySize, GEMM_SMEM);

    // Merged QKV projection
    qkv_proj<<<dim3(QH_ + 2 * KH_, M_ROWS / 128), 256, GEMM_SMEM>>>(x, Wq, Wk, Wv, q, k, v);

    // RoPE (emits tf32-rounded q/k)
    {
        int tq = B_ * S_ * QH_ * (HD_ / 2);
        int tk = B_ * S_ * KH_ * (HD_ / 2);
        rope_kernel<<<(tq + 255) / 256, 256>>>(q, positions, QH_, tq);
        rope_kernel<<<(tk + 255) / 256, 256>>>(k, positions, KH_, tk);
    }

    // Flash attention v2b (race-free softmax state)
    cudaFuncSetAttribute(flash_tc2, cudaFuncAttributeMaxDynamicSharedMemorySize, F2_SMEM);
    flash_tc2<<<dim3(S_ / 128, B_ * QH_), 512, F2_SMEM>>>(q, k, v, att);

    // Output projection
    o_proj<<<dim3(D_ / 128, M_ROWS / 128), 256, GEMM_SMEM>>>(att, Wo, out);
}

// round 8
// speedup vs baseline: 4.1839x; 1.0755x over previous
#include <cuda_runtime.h>
#include <math.h>
#include <stdint.h>

// Problem dimensions (fixed by the dataset)
#define B_  2
#define S_  2048
#define D_  2048
#define QH_ 16
#define KH_ 4
#define HD_ 128
#define M_ROWS (B_ * S_)   // 4096

// ---------------------------------------------------------------------------
// Scratch (no allocations allowed -> __device__ globals)
// ---------------------------------------------------------------------------
__device__ float g_q[B_ * S_ * QH_ * HD_];   // 8M floats
__device__ float g_k[B_ * S_ * KH_ * HD_];   // 2M
__device__ float g_v[B_ * S_ * KH_ * HD_];   // 2M
__device__ float g_att[B_ * S_ * QH_ * HD_]; // 8M
__device__ float g_xr[B_ * S_ * D_];         // 8M  (tf32-rounded x)
__device__ float g_wq[QH_ * D_ * HD_];       // 4M  (tf32-rounded weights)
__device__ float g_wk[KH_ * D_ * HD_];       // 1M
__device__ float g_wv[KH_ * D_ * HD_];       // 1M
__device__ float g_wo[QH_ * HD_ * D_];       // 4M

// ---------------------------------------------------------------------------
// TF32 / cp.async helpers
// ---------------------------------------------------------------------------
__device__ __forceinline__ uint32_t f2tf32(float f) {
    uint32_t u;
    asm("cvt.rna.tf32.f32 %0, %1;" : "=r"(u) : "f"(f));
    return u;
}

__device__ __forceinline__ void mma_tf32(float* c, const uint32_t* a, const uint32_t* b) {
    asm volatile(
        "mma.sync.aligned.m16n8k8.row.col.f32.tf32.tf32.f32 "
        "{%0,%1,%2,%3}, {%4,%5,%6,%7}, {%8,%9}, {%0,%1,%2,%3};\n"
        : "+f"(c[0]), "+f"(c[1]), "+f"(c[2]), "+f"(c[3])
        : "r"(a[0]), "r"(a[1]), "r"(a[2]), "r"(a[3]), "r"(b[0]), "r"(b[1]));
}

__device__ __forceinline__ void cp_async16(void* sptr, const void* gptr) {
    uint32_t sa = (uint32_t)__cvta_generic_to_shared(sptr);
    asm volatile("cp.async.cg.shared.global [%0], [%1], 16;\n" :: "r"(sa), "l"(gptr));
}
#define CP_COMMIT() asm volatile("cp.async.commit_group;\n" ::: "memory")
#define CP_WAIT1()  asm volatile("cp.async.wait_group 1;\n" ::: "memory")

// ---------------------------------------------------------------------------
// Elementwise tf32 rounding pass (vectorized)
// ---------------------------------------------------------------------------
__global__ void round_tf32_kernel(float* __restrict__ dst, const float* __restrict__ src,
                                  int n4) {
    int i = blockIdx.x * blockDim.x + threadIdx.x;
    if (i >= n4) return;
    float4 v = ((const float4*)src)[i];
    uint4 t = make_uint4(f2tf32(v.x), f2tf32(v.y), f2tf32(v.z), f2tf32(v.w));
    ((uint4*)dst)[i] = t;
}

// ---------------------------------------------------------------------------
// Pipelined TF32 GEMM body. 128x128 tile, BK=32, 3-stage cp.async.
// All operands are PRE-ROUNDED to tf32 -> no cvt in the inner loop.
// ROUNDC: epilogue rounds C to tf32 (for tensors consumed raw downstream).
// ---------------------------------------------------------------------------
#define GSTAGES 3
#define ASTG (128 * 36)
#define BSTG (32 * 136)
#define STG_WORDS (ASTG + BSTG)
#define GEMM_SMEM (GSTAGES * STG_WORDS * 4)

template <bool ROUNDC>
__device__ __forceinline__ void gemm_body(const float* __restrict__ A,
                                          const float* __restrict__ Wp,
                                          float* __restrict__ C,
                                          int K, int ldc, int wld,
                                          int brow, int ccol, float* smem) {
    const int tid  = threadIdx.x;
    const int lane = tid & 31;
    const int wid  = tid >> 5;
    const int warpm = wid >> 2;
    const int warpn = wid & 3;
    const int g = lane >> 2;
    const int q = lane & 3;

    const int am  = tid >> 3;
    const int ak4 = (tid & 7) << 2;
    const int bk  = tid >> 5;
    const int bn4 = (tid & 31) << 2;

    const int NITER = K >> 5;

    const float* Abase = A + (size_t)(brow + am) * K + ak4;

    float acc[4][4][4];
#pragma unroll
    for (int mt = 0; mt < 4; mt++)
#pragma unroll
        for (int nt = 0; nt < 4; nt++)
#pragma unroll
            for (int i = 0; i < 4; i++) acc[mt][nt][i] = 0.f;

    auto issue_tile = [&](int t) {
        float* As = smem + (t % GSTAGES) * STG_WORDS;
        float* Bs = As + ASTG;
        const int k0 = t << 5;
        const float* ap = Abase + k0;
#pragma unroll
        for (int p = 0; p < 4; p++)
            cp_async16(As + (am + 32 * p) * 36 + ak4, ap + (size_t)(32 * p) * K);
        const float* wp = Wp + (size_t)(k0 + bk) * wld + bn4;
#pragma unroll
        for (int p = 0; p < 4; p++)
            cp_async16(Bs + (bk + 8 * p) * 136 + bn4, wp + (size_t)(8 * p) * wld);
    };

    issue_tile(0); CP_COMMIT();
    issue_tile(1); CP_COMMIT();

    for (int i = 0; i < NITER; i++) {
        CP_WAIT1();
        __syncthreads();
        if (i + 2 < NITER) issue_tile(i + 2);
        CP_COMMIT();

        const uint32_t* As = (const uint32_t*)(smem + (i % GSTAGES) * STG_WORDS);
        const uint32_t* Bs = As + ASTG;

#pragma unroll
        for (int kk = 0; kk < 4; kk++) {
            const int kc = kk * 8;
            uint32_t af[4][4];
            uint32_t bf[4][2];
#pragma unroll
            for (int mt = 0; mt < 4; mt++) {
                int r = warpm * 64 + mt * 16 + g;
                af[mt][0] = As[r * 36 + kc + q];
                af[mt][1] = As[(r + 8) * 36 + kc + q];
                af[mt][2] = As[r * 36 + kc + q + 4];
                af[mt][3] = As[(r + 8) * 36 + kc + q + 4];
            }
#pragma unroll
            for (int nt = 0; nt < 4; nt++) {
                int c = warpn * 32 + nt * 8 + g;
                bf[nt][0] = Bs[(kc + q) * 136 + c];
                bf[nt][1] = Bs[(kc + q + 4) * 136 + c];
            }
#pragma unroll
            for (int mt = 0; mt < 4; mt++)
#pragma unroll
                for (int nt = 0; nt < 4; nt++)
                    mma_tf32(acc[mt][nt], af[mt], bf[nt]);
        }
    }

#pragma unroll
    for (int mt = 0; mt < 4; mt++) {
        int r = brow + warpm * 64 + mt * 16 + g;
#pragma unroll
        for (int nt = 0; nt < 4; nt++) {
            int c = ccol + warpn * 32 + nt * 8 + 2 * q;
            if (ROUNDC) {
                uint2 c0 = make_uint2(f2tf32(acc[mt][nt][0]), f2tf32(acc[mt][nt][1]));
                uint2 c1 = make_uint2(f2tf32(acc[mt][nt][2]), f2tf32(acc[mt][nt][3]));
                *(uint2*)&C[(size_t)r * ldc + c] = c0;
                *(uint2*)&C[(size_t)(r + 8) * ldc + c] = c1;
            } else {
                *(float2*)&C[(size_t)r * ldc + c] = make_float2(acc[mt][nt][0], acc[mt][nt][1]);
                *(float2*)&C[(size_t)(r + 8) * ldc + c] = make_float2(acc[mt][nt][2], acc[mt][nt][3]);
            }
        }
    }
}

// Merged QKV projection: grid (24 head-blocks, 32 row-blocks)
// V output is tf32-rounded in the epilogue (flash consumes it raw).
__global__ __launch_bounds__(256) void qkv_proj(const float* __restrict__ x,
                                                const float* __restrict__ Wq,
                                                const float* __restrict__ Wk,
                                                const float* __restrict__ Wv,
                                                float* __restrict__ qo,
                                                float* __restrict__ ko,
                                                float* __restrict__ vo) {
    extern __shared__ float sm_f[];
    const int h = blockIdx.x;
    const int brow = blockIdx.y * 128;
    if (h < QH_) {
        gemm_body<false>(x, Wq + (size_t)h * D_ * HD_, qo, D_, QH_ * HD_, HD_, brow, h * HD_, sm_f);
    } else if (h < QH_ + KH_) {
        int hh = h - QH_;
        gemm_body<false>(x, Wk + (size_t)hh * D_ * HD_, ko, D_, KH_ * HD_, HD_, brow, hh * HD_, sm_f);
    } else {
        int hh = h - QH_ - KH_;
        gemm_body<true>(x, Wv + (size_t)hh * D_ * HD_, vo, D_, KH_ * HD_, HD_, brow, hh * HD_, sm_f);
    }
}

// Output projection: grid (16 col-blocks, 32 row-blocks)
__global__ __launch_bounds__(256) void o_proj(const float* __restrict__ att,
                                              const float* __restrict__ Wo,
                                              float* __restrict__ out) {
    extern __shared__ float sm_f[];
    const int bcol = blockIdx.x * 128;
    const int brow = blockIdx.y * 128;
    gemm_body<false>(att, Wo + bcol, out, QH_ * HD_, D_, D_, brow, bcol, sm_f);
}

// ---------------------------------------------------------------------------
// RoPE (in-place) on [B, S, NH, 128]. Writes tf32-rounded values.
// ---------------------------------------------------------------------------
__global__ void rope_kernel(float* __restrict__ x, const int* __restrict__ positions,
                            int NH, int total) {
    int i = blockIdx.x * blockDim.x + threadIdx.x;
    if (i >= total) return;
    int hp = i & 63;
    int rest = i >> 6;
    int nh = rest % NH;
    int s  = (rest / NH) % S_;
    int b  = rest / (NH * S_);

    float pos = (float)positions[s];
    float ts  = expf(((float)hp / 64.f) * 9.21034037197618f /* ln(1e4) */);
    float ang = pos / ts;
    float sn = sinf(ang);
    float cs = cosf(ang);

    size_t base = ((size_t)(b * S_ + s) * NH + nh) * HD_;
    float x1 = x[base + hp];
    float x2 = x[base + hp + 64];
    x[base + hp]      = __uint_as_float(f2tf32(x1 * cs - x2 * sn));
    x[base + hp + 64] = __uint_as_float(f2tf32(x2 * cs + x1 * sn));
}

// ---------------------------------------------------------------------------
// Flash attention v2b: TF32 tensor cores, causal, GQA.
// 128-query tiles, 512 threads = 16 warps (4m x 4n).
// Q/K/V all pre-rounded tf32 -> no cvt on fragment loads.
// Epilogue writes tf32-rounded att (o_proj consumes raw).
// ---------------------------------------------------------------------------
#define QS2 136
#define KS2 132
#define VS2 136
#define PS2 72
#define KTILE_W (64 * KS2)

#define F2_SMEM ((128 * QS2 + 2 * KTILE_W + 64 * VS2 + 128 * PS2 + 512 + 512) * 4)

__global__ __launch_bounds__(512) void flash_tc2(const float* __restrict__ Q,
                                                 const float* __restrict__ K,
                                                 const float* __restrict__ V,
                                                 float* __restrict__ O) {
    extern __shared__ uint32_t sm_u[];
    uint32_t* Qs = sm_u;                    // [128][136] pair layout
    uint32_t* Kb = Qs + 128 * QS2;          // 2 x [64][132] natural
    uint32_t* Vs = Kb + 2 * KTILE_W;        // [64][136] natural
    uint32_t* Ps = Vs + 64 * VS2;           // [128][72] pair layout
    float* smax  = (float*)(Ps + 128 * PS2);   // [4][128]
    float* ssum  = smax + 512;                 // [4][128]

    const int tid  = threadIdx.x;
    const int lane = tid & 31;
    const int wid  = tid >> 5;
    const int warpm = wid >> 2;   // 0..3
    const int warpn = wid & 3;    // 0..3
    const int g = lane >> 2;      // 0..7
    const int q = lane & 3;       // 0..3

    const int mblk = gridDim.x - 1 - blockIdx.x;   // heavy tiles first
    const int bq = blockIdx.y;
    const int b  = bq / QH_;
    const int qh = bq % QH_;
    const int kvh = qh / (QH_ / KH_);

    // ---- load Q tile [128][128] into pair layout (pre-rounded tf32) ----
    for (int idx = tid; idx < 128 * 32; idx += 512) {
        int r  = idx >> 5;
        int c4 = (idx & 31) << 2;
        float4 v4 = *(const float4*)(Q + ((size_t)(b * S_ + mblk * 128 + r) * QH_ + qh) * HD_ + c4);
        uint32_t* dst = Qs + r * QS2 + ((c4 >> 3) << 3) + ((c4 >> 2) & 1);
        dst[0] = __float_as_uint(v4.x);
        dst[2] = __float_as_uint(v4.y);
        dst[4] = __float_as_uint(v4.z);
        dst[6] = __float_as_uint(v4.w);
    }

    float rmr[2][2], rlr[2][2];
#pragma unroll
    for (int mt = 0; mt < 2; mt++)
#pragma unroll
        for (int h = 0; h < 2; h++) { rmr[mt][h] = -INFINITY; rlr[mt][h] = 0.f; }

    float o[2][4][4];
#pragma unroll
    for (int mt = 0; mt < 2; mt++)
#pragma unroll
        for (int nt = 0; nt < 4; nt++)
#pragma unroll
            for (int i = 0; i < 4; i++) o[mt][nt][i] = 0.f;

    const float scale = 0.08838834764831845f;  // 1/sqrt(128)
    const int row_base = warpm * 32 + g;
    const int qkcol_base = warpn * 16 + 2 * q;
    const int NIT = 2 * mblk + 2;

    auto issueK = [&](int n) {
        uint32_t* kd = Kb + (n & 1) * KTILE_W;
        for (int idx = tid; idx < 64 * 32; idx += 512) {
            int r  = idx >> 5;
            int c4 = (idx & 31) << 2;
            cp_async16(kd + r * KS2 + c4,
                       K + ((size_t)(b * S_ + n * 64 + r) * KH_ + kvh) * HD_ + c4);
        }
    };
    auto issueV = [&](int n) {
        for (int idx = tid; idx < 64 * 32; idx += 512) {
            int r  = idx >> 5;
            int c4 = (idx & 31) << 2;
            cp_async16(Vs + r * VS2 + c4,
                       V + ((size_t)(b * S_ + n * 64 + r) * KH_ + kvh) * HD_ + c4);
        }
    };

    issueK(0); issueV(0); CP_COMMIT();

    for (int n = 0; n < NIT; n++) {
        if (n + 1 < NIT) issueK(n + 1);
        CP_COMMIT();
        CP_WAIT1();
        __syncthreads();           // A: K(n),V(n) ready

        const uint32_t* Kst = Kb + (n & 1) * KTILE_W;

        // ---- QK^T ----
        float s[2][2][4];
#pragma unroll
        for (int mt = 0; mt < 2; mt++)
#pragma unroll
            for (int nt = 0; nt < 2; nt++)
#pragma unroll
                for (int i = 0; i < 4; i++) s[mt][nt][i] = 0.f;

#pragma unroll
        for (int ks = 0; ks < 16; ks++) {
            const int kc = ks * 8;
            uint32_t af[2][4], bf[2][2];
#pragma unroll
            for (int mt = 0; mt < 2; mt++) {
                int r = warpm * 32 + mt * 16 + g;
                uint2 a0 = *(const uint2*)&Qs[r * QS2 + kc + q * 2];
                uint2 a1 = *(const uint2*)&Qs[(r + 8) * QS2 + kc + q * 2];
                af[mt][0] = a0.x; af[mt][2] = a0.y;
                af[mt][1] = a1.x; af[mt][3] = a1.y;
            }
#pragma unroll
            for (int nt = 0; nt < 2; nt++) {
                int c = warpn * 16 + nt * 8 + g;
                bf[nt][0] = Kst[c * KS2 + kc + q];
                bf[nt][1] = Kst[c * KS2 + kc + q + 4];
            }
#pragma unroll
            for (int mt = 0; mt < 2; mt++)
#pragma unroll
                for (int nt = 0; nt < 2; nt++)
                    mma_tf32(s[mt][nt], af[mt], bf[nt]);
        }

        // ---- scale + causal mask ----
        if (n >= 2 * mblk) {
            const int gr_base = mblk * 128 + row_base;
            const int gc_base = n * 64 + qkcol_base;
#pragma unroll
            for (int mt = 0; mt < 2; mt++) {
                int gr0 = gr_base + mt * 16;
                int gr1 = gr0 + 8;
#pragma unroll
                for (int nt = 0; nt < 2; nt++) {
                    int gc0 = gc_base + nt * 8;
                    int gc1 = gc0 + 1;
                    s[mt][nt][0] = (gc0 > gr0) ? -1e9f : s[mt][nt][0] * scale;
                    s[mt][nt][1] = (gc1 > gr0) ? -1e9f : s[mt][nt][1] * scale;
                    s[mt][nt][2] = (gc0 > gr1) ? -1e9f : s[mt][nt][2] * scale;
                    s[mt][nt][3] = (gc1 > gr1) ? -1e9f : s[mt][nt][3] * scale;
                }
            }
        } else {
#pragma unroll
            for (int mt = 0; mt < 2; mt++)
#pragma unroll
                for (int nt = 0; nt < 2; nt++)
#pragma unroll
                    for (int i = 0; i < 4; i++) s[mt][nt][i] *= scale;
        }

        // ---- partial row max -> smax ----
#pragma unroll
        for (int mt = 0; mt < 2; mt++)
#pragma unroll
            for (int h = 0; h < 2; h++) {
                float pm = fmaxf(fmaxf(s[mt][0][2 * h], s[mt][0][2 * h + 1]),
                                 fmaxf(s[mt][1][2 * h], s[mt][1][2 * h + 1]));
                pm = fmaxf(pm, __shfl_xor_sync(0xFFFFFFFF, pm, 1));
                pm = fmaxf(pm, __shfl_xor_sync(0xFFFFFFFF, pm, 2));
                if (q == 0) smax[warpn * 128 + row_base + mt * 16 + 8 * h] = pm;
            }
        __syncthreads();           // B: smax complete

        // ---- m update (registers), exp, P store, partial sums ----
        const int poff0 = (((2 * q) & 3) << 1) + (q >> 1);
        const int poff1 = (((2 * q + 1) & 3) << 1) + ((2 * q + 1) >> 2);
        float corr[2][2];
#pragma unroll
        for (int mt = 0; mt < 2; mt++)
#pragma unroll
            for (int h = 0; h < 2; h++) {
                int row = row_base + mt * 16 + 8 * h;
                float m_tile = fmaxf(fmaxf(smax[row], smax[128 + row]),
                                     fmaxf(smax[256 + row], smax[384 + row]));
                float m_old = rmr[mt][h];
                float m_new = fmaxf(m_old, m_tile);
                corr[mt][h] = __expf(m_old - m_new);
                rmr[mt][h] = m_new;

                float psum = 0.f;
#pragma unroll
                for (int nt = 0; nt < 2; nt++) {
                    float p0 = __expf(s[mt][nt][2 * h] - m_new);
                    float p1 = __expf(s[mt][nt][2 * h + 1] - m_new);
                    psum += p0 + p1;
                    uint32_t* pb = Ps + row * PS2 + (warpn * 2 + nt) * 8;
                    pb[poff0] = f2tf32(p0);
                    pb[poff1] = f2tf32(p1);
                }
                psum += __shfl_xor_sync(0xFFFFFFFF, psum, 1);
                psum += __shfl_xor_sync(0xFFFFFFFF, psum, 2);
                if (q == 0) ssum[warpn * 128 + row] = psum;
            }
        __syncthreads();           // C: Ps + ssum complete

        // ---- l update (registers) ----
#pragma unroll
        for (int mt = 0; mt < 2; mt++)
#pragma unroll
            for (int h = 0; h < 2; h++) {
                int row = row_base + mt * 16 + 8 * h;
                float ts = ssum[row] + ssum[128 + row] + ssum[256 + row] + ssum[384 + row];
                rlr[mt][h] = rlr[mt][h] * corr[mt][h] + ts;
            }

        // ---- rescale O, then PV mma ----
#pragma unroll
        for (int mt = 0; mt < 2; mt++)
#pragma unroll
            for (int nt = 0; nt < 4; nt++) {
                o[mt][nt][0] *= corr[mt][0];
                o[mt][nt][1] *= corr[mt][0];
                o[mt][nt][2] *= corr[mt][1];
                o[mt][nt][3] *= corr[mt][1];
            }

#pragma unroll
        for (int ks = 0; ks < 8; ks++) {
            const int kc = ks * 8;
            uint32_t af[2][4], bf[4][2];
#pragma unroll
            for (int mt = 0; mt < 2; mt++) {
                int r = warpm * 32 + mt * 16 + g;
                uint2 a0 = *(const uint2*)&Ps[r * PS2 + kc + q * 2];
                uint2 a1 = *(const uint2*)&Ps[(r + 8) * PS2 + kc + q * 2];
                af[mt][0] = a0.x; af[mt][2] = a0.y;
                af[mt][1] = a1.x; af[mt][3] = a1.y;
            }
#pragma unroll
            for (int nt = 0; nt < 4; nt++) {
                int c = warpn * 32 + nt * 8 + g;
                bf[nt][0] = Vs[(kc + q) * VS2 + c];        // V pre-rounded tf32
                bf[nt][1] = Vs[(kc + q + 4) * VS2 + c];
            }
#pragma unroll
            for (int mt = 0; mt < 2; mt++)
#pragma unroll
                for (int nt = 0; nt < 4; nt++)
                    mma_tf32(o[mt][nt], af[mt], bf[nt]);
        }

        __syncthreads();           // D: all warps done with Ps/Vs
        if (n + 1 < NIT) issueV(n + 1);
        CP_COMMIT();
    }

    // ---- epilogue: normalize + round to tf32 (o_proj consumes raw) ----
#pragma unroll
    for (int mt = 0; mt < 2; mt++) {
        float inv0 = 1.0f / rlr[mt][0];
        float inv1 = 1.0f / rlr[mt][1];
        int s0 = mblk * 128 + row_base + mt * 16;
#pragma unroll
        for (int nt = 0; nt < 4; nt++) {
            int col = warpn * 32 + nt * 8 + 2 * q;
            float* op0 = O + ((size_t)(b * S_ + s0) * QH_ + qh) * HD_ + col;
            float* op1 = O + ((size_t)(b * S_ + s0 + 8) * QH_ + qh) * HD_ + col;
            *(uint2*)op0 = make_uint2(f2tf32(o[mt][nt][0] * inv0), f2tf32(o[mt][nt][1] * inv0));
            *(uint2*)op1 = make_uint2(f2tf32(o[mt][nt][2] * inv1), f2tf32(o[mt][nt][3] * inv1));
        }
    }
}

// ---------------------------------------------------------------------------
// Launch
// ---------------------------------------------------------------------------
extern "C" void kernel_launch(void* const* d_in, const int* in_sizes, int n_in,
                              void* d_out, int out_size) {
    const float* x         = (const float*)d_in[0];
    const int*   positions = (const int*)d_in[1];
    const float* Wq        = (const float*)d_in[2];
    const float* Wk        = (const float*)d_in[3];
    const float* Wv        = (const float*)d_in[4];
    const float* Wo        = (const float*)d_in[5];
    float* out = (float*)d_out;

    float *q, *k, *v, *att, *xr, *wq, *wk, *wv, *wo;
    cudaGetSymbolAddress((void**)&q,   g_q);
    cudaGetSymbolAddress((void**)&k,   g_k);
    cudaGetSymbolAddress((void**)&v,   g_v);
    cudaGetSymbolAddress((void**)&att, g_att);
    cudaGetSymbolAddress((void**)&xr,  g_xr);
    cudaGetSymbolAddress((void**)&wq,  g_wq);
    cudaGetSymbolAddress((void**)&wk,  g_wk);
    cudaGetSymbolAddress((void**)&wv,  g_wv);
    cudaGetSymbolAddress((void**)&wo,  g_wo);

    cudaFuncSetAttribute(qkv_proj, cudaFuncAttributeMaxDynamicSharedMemorySize, GEMM_SMEM);
    cudaFuncSetAttribute(o_proj,   cudaFuncAttributeMaxDynamicSharedMemorySize, GEMM_SMEM);
    cudaFuncSetAttribute(flash_tc2, cudaFuncAttributeMaxDynamicSharedMemorySize, F2_SMEM);

    // Pre-round operands to tf32 (hoisted cvt.rna; bit-identical dataflow)
    {
        int nx = B_ * S_ * D_ / 4;
        round_tf32_kernel<<<(nx + 255) / 256, 256>>>(xr, x, nx);
        int nq = QH_ * D_ * HD_ / 4;
        round_tf32_kernel<<<(nq + 255) / 256, 256>>>(wq, Wq, nq);
        int nk = KH_ * D_ * HD_ / 4;
        round_tf32_kernel<<<(nk + 255) / 256, 256>>>(wk, Wk, nk);
        round_tf32_kernel<<<(nk + 255) / 256, 256>>>(wv, Wv, nk);
        int no = QH_ * HD_ * D_ / 4;
        round_tf32_kernel<<<(no + 255) / 256, 256>>>(wo, Wo, no);
    }

    // Merged QKV projection (cvt-free inner loop)
    qkv_proj<<<dim3(QH_ + 2 * KH_, M_ROWS / 128), 256, GEMM_SMEM>>>(xr, wq, wk, wv, q, k, v);

    // RoPE (emits tf32-rounded q/k)
    {
        int tq = B_ * S_ * QH_ * (HD_ / 2);
        int tk = B_ * S_ * KH_ * (HD_ / 2);
        rope_kernel<<<(tq + 255) / 256, 256>>>(q, positions, QH_, tq);
        rope_kernel<<<(tk + 255) / 256, 256>>>(k, positions, KH_, tk);
    }

    // Flash attention v2b (cvt-free fragment loads)
    flash_tc2<<<dim3(S_ / 128, B_ * QH_), 512, F2_SMEM>>>(q, k, v, att);

    // Output projection (cvt-free)
    o_proj<<<dim3(D_ / 128, M_ROWS / 128), 256, GEMM_SMEM>>>(att, wo, out);
}

// round 10
// speedup vs baseline: 4.3131x; 1.0309x over previous
#include <cuda_runtime.h>
#include <math.h>
#include <stdint.h>

// Problem dimensions (fixed by the dataset)
#define B_  2
#define S_  2048
#define D_  2048
#define QH_ 16
#define KH_ 4
#define HD_ 128
#define M_ROWS (B_ * S_)   // 4096

// ---------------------------------------------------------------------------
// Scratch (no allocations allowed -> __device__ globals)
// ---------------------------------------------------------------------------
__device__ float g_q[B_ * S_ * QH_ * HD_];   // 8M floats
__device__ float g_k[B_ * S_ * KH_ * HD_];   // 2M
__device__ float g_v[B_ * S_ * KH_ * HD_];   // 2M
__device__ float g_att[B_ * S_ * QH_ * HD_]; // 8M
__device__ float g_xr[B_ * S_ * D_];         // 8M  (tf32-rounded x)
__device__ float g_wq[QH_ * D_ * HD_];       // 4M  (tf32-rounded weights)
__device__ float g_wk[KH_ * D_ * HD_];       // 1M
__device__ float g_wv[KH_ * D_ * HD_];       // 1M
__device__ float g_wo[QH_ * HD_ * D_];       // 4M

// ---------------------------------------------------------------------------
// TF32 / cp.async helpers
// ---------------------------------------------------------------------------
__device__ __forceinline__ uint32_t f2tf32(float f) {
    uint32_t u;
    asm("cvt.rna.tf32.f32 %0, %1;" : "=r"(u) : "f"(f));
    return u;
}

__device__ __forceinline__ void mma_tf32(float* c, const uint32_t* a, const uint32_t* b) {
    asm volatile(
        "mma.sync.aligned.m16n8k8.row.col.f32.tf32.tf32.f32 "
        "{%0,%1,%2,%3}, {%4,%5,%6,%7}, {%8,%9}, {%0,%1,%2,%3};\n"
        : "+f"(c[0]), "+f"(c[1]), "+f"(c[2]), "+f"(c[3])
        : "r"(a[0]), "r"(a[1]), "r"(a[2]), "r"(a[3]), "r"(b[0]), "r"(b[1]));
}

__device__ __forceinline__ void cp_async16(void* sptr, const void* gptr) {
    uint32_t sa = (uint32_t)__cvta_generic_to_shared(sptr);
    asm volatile("cp.async.cg.shared.global [%0], [%1], 16;\n" :: "r"(sa), "l"(gptr));
}
#define CP_COMMIT() asm volatile("cp.async.commit_group;\n" ::: "memory")
#define CP_WAIT1()  asm volatile("cp.async.wait_group 1;\n" ::: "memory")

// ---------------------------------------------------------------------------
// Elementwise tf32 rounding pass (vectorized)
// ---------------------------------------------------------------------------
__global__ void round_tf32_kernel(float* __restrict__ dst, const float* __restrict__ src,
                                  int n4) {
    int i = blockIdx.x * blockDim.x + threadIdx.x;
    if (i >= n4) return;
    float4 v = ((const float4*)src)[i];
    uint4 t = make_uint4(f2tf32(v.x), f2tf32(v.y), f2tf32(v.z), f2tf32(v.w));
    ((uint4*)dst)[i] = t;
}

// ---------------------------------------------------------------------------
// Pipelined TF32 GEMM body v2. CTA tile 128x256, BK=32, 3-stage cp.async.
// 256 threads = 8 warps (2m x 4n), warp tile 64x64, m16n8k8.
// Operands pre-rounded tf32 -> no cvt in inner loop.
// Smem: As[m][k] stride 36 (conflict-free A frags),
//       Bs[k][n] stride 264 (bank = 8q + g, conflict-free B frags).
// HEADB: W is the first of two consecutive [K][128] head blocks; column >=128
//        selects the second head block. Otherwise W is [K][wld] pre-offset.
// ROUNDC: epilogue rounds C to tf32.
// ---------------------------------------------------------------------------
#define GSTAGES 3
#define ASTG (128 * 36)
#define BSTG (32 * 264)
#define STG_WORDS (ASTG + BSTG)
#define GEMM_SMEM (GSTAGES * STG_WORDS * 4)

template <bool HEADB, bool ROUNDC>
__device__ __forceinline__ void gemm_body(const float* __restrict__ A,
                                          const float* __restrict__ W,
                                          float* __restrict__ C,
                                          int K, int ldc, int wld,
                                          int brow, int ccol, float* smem) {
    const int tid  = threadIdx.x;
    const int lane = tid & 31;
    const int wid  = tid >> 5;
    const int warpm = wid >> 2;        // 0..1 (64-row slices)
    const int warpn = wid & 3;         // 0..3 (64-col slices)
    const int g = lane >> 2;
    const int q = lane & 3;

    // A loader: 128 rows x 32 cols, 4 x 16B per thread
    const int am  = tid >> 3;          // 0..31
    const int ak4 = (tid & 7) << 2;    // 0..28
    // B loader: 32 rows x 256 cols, 8 x 16B per thread
    const int NITER = K >> 5;

    const float* Abase = A + (size_t)(brow + am) * K + ak4;

    float acc[4][8][4];
#pragma unroll
    for (int mt = 0; mt < 4; mt++)
#pragma unroll
        for (int nt = 0; nt < 8; nt++)
#pragma unroll
            for (int i = 0; i < 4; i++) acc[mt][nt][i] = 0.f;

    auto issue_tile = [&](int t) {
        float* As = smem + (t % GSTAGES) * STG_WORDS;
        float* Bs = As + ASTG;
        const int k0 = t << 5;
        const float* ap = Abase + k0;
#pragma unroll
        for (int p = 0; p < 4; p++)
            cp_async16(As + (am + 32 * p) * 36 + ak4, ap + (size_t)(32 * p) * K);
#pragma unroll
        for (int p = 0; p < 8; p++) {
            int idx = tid + p * 256;       // 0..2047
            int row = idx >> 6;            // 0..31
            int c4  = (idx & 63) << 2;     // 0..252
            const float* wp;
            if (HEADB) {
                // two consecutive [K][128] head blocks
                wp = W + (size_t)(c4 >> 7) * K * 128 + (size_t)(k0 + row) * 128 + (c4 & 127);
            } else {
                wp = W + (size_t)(k0 + row) * wld + c4;
            }
            cp_async16(Bs + row * 264 + c4, wp);
        }
    };

    issue_tile(0); CP_COMMIT();
    issue_tile(1); CP_COMMIT();

    for (int i = 0; i < NITER; i++) {
        CP_WAIT1();
        __syncthreads();
        if (i + 2 < NITER) issue_tile(i + 2);
        CP_COMMIT();

        const uint32_t* As = (const uint32_t*)(smem + (i % GSTAGES) * STG_WORDS);
        const uint32_t* Bs = As + ASTG;

#pragma unroll
        for (int kk = 0; kk < 4; kk++) {
            const int kc = kk * 8;
            uint32_t af[4][4];
            uint32_t bf[8][2];
#pragma unroll
            for (int mt = 0; mt < 4; mt++) {
                int r = warpm * 64 + mt * 16 + g;
                af[mt][0] = As[r * 36 + kc + q];
                af[mt][1] = As[(r + 8) * 36 + kc + q];
                af[mt][2] = As[r * 36 + kc + q + 4];
                af[mt][3] = As[(r + 8) * 36 + kc + q + 4];
            }
#pragma unroll
            for (int nt = 0; nt < 8; nt++) {
                int c = warpn * 64 + nt * 8 + g;
                bf[nt][0] = Bs[(kc + q) * 264 + c];
                bf[nt][1] = Bs[(kc + q + 4) * 264 + c];
            }
#pragma unroll
            for (int mt = 0; mt < 4; mt++)
#pragma unroll
                for (int nt = 0; nt < 8; nt++)
                    mma_tf32(acc[mt][nt], af[mt], bf[nt]);
        }
    }

    // ---- epilogue ----
#pragma unroll
    for (int mt = 0; mt < 4; mt++) {
        int r = brow + warpm * 64 + mt * 16 + g;
#pragma unroll
        for (int nt = 0; nt < 8; nt++) {
            int c = ccol + warpn * 64 + nt * 8 + 2 * q;
            if (ROUNDC) {
                uint2 c0 = make_uint2(f2tf32(acc[mt][nt][0]), f2tf32(acc[mt][nt][1]));
                uint2 c1 = make_uint2(f2tf32(acc[mt][nt][2]), f2tf32(acc[mt][nt][3]));
                *(uint2*)&C[(size_t)r * ldc + c] = c0;
                *(uint2*)&C[(size_t)(r + 8) * ldc + c] = c1;
            } else {
                *(float2*)&C[(size_t)r * ldc + c] = make_float2(acc[mt][nt][0], acc[mt][nt][1]);
                *(float2*)&C[(size_t)(r + 8) * ldc + c] = make_float2(acc[mt][nt][2], acc[mt][nt][3]);
            }
        }
    }
}

// Merged QKV projection: grid (12 head-pair blocks, 32 row-blocks)
// hp 0..7 -> Q head pairs; 8..9 -> K; 10..11 -> V (rounded output).
__global__ __launch_bounds__(256) void qkv_proj(const float* __restrict__ x,
                                                const float* __restrict__ Wq,
                                                const float* __restrict__ Wk,
                                                const float* __restrict__ Wv,
                                                float* __restrict__ qo,
                                                float* __restrict__ ko,
                                                float* __restrict__ vo) {
    extern __shared__ float sm_f[];
    const int hp = blockIdx.x;
    const int brow = blockIdx.y * 128;
    if (hp < 8) {
        gemm_body<true, false>(x, Wq + (size_t)(2 * hp) * D_ * HD_, qo,
                               D_, QH_ * HD_, HD_, brow, hp * 256, sm_f);
    } else if (hp < 10) {
        int p = hp - 8;
        gemm_body<true, false>(x, Wk + (size_t)(2 * p) * D_ * HD_, ko,
                               D_, KH_ * HD_, HD_, brow, p * 256, sm_f);
    } else {
        int p = hp - 10;
        gemm_body<true, true>(x, Wv + (size_t)(2 * p) * D_ * HD_, vo,
                              D_, KH_ * HD_, HD_, brow, p * 256, sm_f);
    }
}

// Output projection: grid (8 col-blocks of 256, 32 row-blocks)
__global__ __launch_bounds__(256) void o_proj(const float* __restrict__ att,
                                              const float* __restrict__ Wo,
                                              float* __restrict__ out) {
    extern __shared__ float sm_f[];
    const int bcol = blockIdx.x * 256;
    const int brow = blockIdx.y * 128;
    gemm_body<false, false>(att, Wo + bcol, out, QH_ * HD_, D_, D_, brow, bcol, sm_f);
}

// ---------------------------------------------------------------------------
// RoPE (in-place) on [B, S, NH, 128]. Writes tf32-rounded values.
// ---------------------------------------------------------------------------
__global__ void rope_kernel(float* __restrict__ x, const int* __restrict__ positions,
                            int NH, int total) {
    int i = blockIdx.x * blockDim.x + threadIdx.x;
    if (i >= total) return;
    int hp = i & 63;
    int rest = i >> 6;
    int nh = rest % NH;
    int s  = (rest / NH) % S_;
    int b  = rest / (NH * S_);

    float pos = (float)positions[s];
    float ts  = expf(((float)hp / 64.f) * 9.21034037197618f /* ln(1e4) */);
    float ang = pos / ts;
    float sn = sinf(ang);
    float cs = cosf(ang);

    size_t base = ((size_t)(b * S_ + s) * NH + nh) * HD_;
    float x1 = x[base + hp];
    float x2 = x[base + hp + 64];
    x[base + hp]      = __uint_as_float(f2tf32(x1 * cs - x2 * sn));
    x[base + hp + 64] = __uint_as_float(f2tf32(x2 * cs + x1 * sn));
}

// ---------------------------------------------------------------------------
// Flash attention v2b (unchanged from R7, passing @ 417us)
// ---------------------------------------------------------------------------
#define QS2 136
#define KS2 132
#define VS2 136
#define PS2 72
#define KTILE_W (64 * KS2)

#define F2_SMEM ((128 * QS2 + 2 * KTILE_W + 64 * VS2 + 128 * PS2 + 512 + 512) * 4)

__global__ __launch_bounds__(512) void flash_tc2(const float* __restrict__ Q,
                                                 const float* __restrict__ K,
                                                 const float* __restrict__ V,
                                                 float* __restrict__ O) {
    extern __shared__ uint32_t sm_u[];
    uint32_t* Qs = sm_u;                    // [128][136] pair layout
    uint32_t* Kb = Qs + 128 * QS2;          // 2 x [64][132] natural
    uint32_t* Vs = Kb + 2 * KTILE_W;        // [64][136] natural
    uint32_t* Ps = Vs + 64 * VS2;           // [128][72] pair layout
    float* smax  = (float*)(Ps + 128 * PS2);   // [4][128]
    float* ssum  = smax + 512;                 // [4][128]

    const int tid  = threadIdx.x;
    const int lane = tid & 31;
    const int wid  = tid >> 5;
    const int warpm = wid >> 2;
    const int warpn = wid & 3;
    const int g = lane >> 2;
    const int q = lane & 3;

    const int mblk = gridDim.x - 1 - blockIdx.x;
    const int bq = blockIdx.y;
    const int b  = bq / QH_;
    const int qh = bq % QH_;
    const int kvh = qh / (QH_ / KH_);

    for (int idx = tid; idx < 128 * 32; idx += 512) {
        int r  = idx >> 5;
        int c4 = (idx & 31) << 2;
        float4 v4 = *(const float4*)(Q + ((size_t)(b * S_ + mblk * 128 + r) * QH_ + qh) * HD_ + c4);
        uint32_t* dst = Qs + r * QS2 + ((c4 >> 3) << 3) + ((c4 >> 2) & 1);
        dst[0] = __float_as_uint(v4.x);
        dst[2] = __float_as_uint(v4.y);
        dst[4] = __float_as_uint(v4.z);
        dst[6] = __float_as_uint(v4.w);
    }

    float rmr[2][2], rlr[2][2];
#pragma unroll
    for (int mt = 0; mt < 2; mt++)
#pragma unroll
        for (int h = 0; h < 2; h++) { rmr[mt][h] = -INFINITY; rlr[mt][h] = 0.f; }

    float o[2][4][4];
#pragma unroll
    for (int mt = 0; mt < 2; mt++)
#pragma unroll
        for (int nt = 0; nt < 4; nt++)
#pragma unroll
            for (int i = 0; i < 4; i++) o[mt][nt][i] = 0.f;

    const float scale = 0.08838834764831845f;  // 1/sqrt(128)
    const int row_base = warpm * 32 + g;
    const int qkcol_base = warpn * 16 + 2 * q;
    const int NIT = 2 * mblk + 2;

    auto issueK = [&](int n) {
        uint32_t* kd = Kb + (n & 1) * KTILE_W;
        for (int idx = tid; idx < 64 * 32; idx += 512) {
            int r  = idx >> 5;
            int c4 = (idx & 31) << 2;
            cp_async16(kd + r * KS2 + c4,
                       K + ((size_t)(b * S_ + n * 64 + r) * KH_ + kvh) * HD_ + c4);
        }
    };
    auto issueV = [&](int n) {
        for (int idx = tid; idx < 64 * 32; idx += 512) {
            int r  = idx >> 5;
            int c4 = (idx & 31) << 2;
            cp_async16(Vs + r * VS2 + c4,
                       V + ((size_t)(b * S_ + n * 64 + r) * KH_ + kvh) * HD_ + c4);
        }
    };

    issueK(0); issueV(0); CP_COMMIT();

    for (int n = 0; n < NIT; n++) {
        if (n + 1 < NIT) issueK(n + 1);
        CP_COMMIT();
        CP_WAIT1();
        __syncthreads();           // A: K(n),V(n) ready

        const uint32_t* Kst = Kb + (n & 1) * KTILE_W;

        float s[2][2][4];
#pragma unroll
        for (int mt = 0; mt < 2; mt++)
#pragma unroll
            for (int nt = 0; nt < 2; nt++)
#pragma unroll
                for (int i = 0; i < 4; i++) s[mt][nt][i] = 0.f;

#pragma unroll
        for (int ks = 0; ks < 16; ks++) {
            const int kc = ks * 8;
            uint32_t af[2][4], bf[2][2];
#pragma unroll
            for (int mt = 0; mt < 2; mt++) {
                int r = warpm * 32 + mt * 16 + g;
                uint2 a0 = *(const uint2*)&Qs[r * QS2 + kc + q * 2];
                uint2 a1 = *(const uint2*)&Qs[(r + 8) * QS2 + kc + q * 2];
                af[mt][0] = a0.x; af[mt][2] = a0.y;
                af[mt][1] = a1.x; af[mt][3] = a1.y;
            }
#pragma unroll
            for (int nt = 0; nt < 2; nt++) {
                int c = warpn * 16 + nt * 8 + g;
                bf[nt][0] = Kst[c * KS2 + kc + q];
                bf[nt][1] = Kst[c * KS2 + kc + q + 4];
            }
#pragma unroll
            for (int mt = 0; mt < 2; mt++)
#pragma unroll
                for (int nt = 0; nt < 2; nt++)
                    mma_tf32(s[mt][nt], af[mt], bf[nt]);
        }

        if (n >= 2 * mblk) {
            const int gr_base = mblk * 128 + row_base;
            const int gc_base = n * 64 + qkcol_base;
#pragma unroll
            for (int mt = 0; mt < 2; mt++) {
                int gr0 = gr_base + mt * 16;
                int gr1 = gr0 + 8;
#pragma unroll
                for (int nt = 0; nt < 2; nt++) {
                    int gc0 = gc_base + nt * 8;
                    int gc1 = gc0 + 1;
                    s[mt][nt][0] = (gc0 > gr0) ? -1e9f : s[mt][nt][0] * scale;
                    s[mt][nt][1] = (gc1 > gr0) ? -1e9f : s[mt][nt][1] * scale;
                    s[mt][nt][2] = (gc0 > gr1) ? -1e9f : s[mt][nt][2] * scale;
                    s[mt][nt][3] = (gc1 > gr1) ? -1e9f : s[mt][nt][3] * scale;
                }
            }
        } else {
#pragma unroll
            for (int mt = 0; mt < 2; mt++)
#pragma unroll
                for (int nt = 0; nt < 2; nt++)
#pragma unroll
                    for (int i = 0; i < 4; i++) s[mt][nt][i] *= scale;
        }

#pragma unroll
        for (int mt = 0; mt < 2; mt++)
#pragma unroll
            for (int h = 0; h < 2; h++) {
                float pm = fmaxf(fmaxf(s[mt][0][2 * h], s[mt][0][2 * h + 1]),
                                 fmaxf(s[mt][1][2 * h], s[mt][1][2 * h + 1]));
                pm = fmaxf(pm, __shfl_xor_sync(0xFFFFFFFF, pm, 1));
                pm = fmaxf(pm, __shfl_xor_sync(0xFFFFFFFF, pm, 2));
                if (q == 0) smax[warpn * 128 + row_base + mt * 16 + 8 * h] = pm;
            }
        __syncthreads();           // B: smax complete

        const int poff0 = (((2 * q) & 3) << 1) + (q >> 1);
        const int poff1 = (((2 * q + 1) & 3) << 1) + ((2 * q + 1) >> 2);
        float corr[2][2];
#pragma unroll
        for (int mt = 0; mt < 2; mt++)
#pragma unroll
            for (int h = 0; h < 2; h++) {
                int row = row_base + mt * 16 + 8 * h;
                float m_tile = fmaxf(fmaxf(smax[row], smax[128 + row]),
                                     fmaxf(smax[256 + row], smax[384 + row]));
                float m_old = rmr[mt][h];
                float m_new = fmaxf(m_old, m_tile);
                corr[mt][h] = __expf(m_old - m_new);
                rmr[mt][h] = m_new;

                float psum = 0.f;
#pragma unroll
                for (int nt = 0; nt < 2; nt++) {
                    float p0 = __expf(s[mt][nt][2 * h] - m_new);
                    float p1 = __expf(s[mt][nt][2 * h + 1] - m_new);
                    psum += p0 + p1;
                    uint32_t* pb = Ps + row * PS2 + (warpn * 2 + nt) * 8;
                    pb[poff0] = f2tf32(p0);
                    pb[poff1] = f2tf32(p1);
                }
                psum += __shfl_xor_sync(0xFFFFFFFF, psum, 1);
                psum += __shfl_xor_sync(0xFFFFFFFF, psum, 2);
                if (q == 0) ssum[warpn * 128 + row] = psum;
            }
        __syncthreads();           // C: Ps + ssum complete

#pragma unroll
        for (int mt = 0; mt < 2; mt++)
#pragma unroll
            for (int h = 0; h < 2; h++) {
                int row = row_base + mt * 16 + 8 * h;
                float ts = ssum[row] + ssum[128 + row] + ssum[256 + row] + ssum[384 + row];
                rlr[mt][h] = rlr[mt][h] * corr[mt][h] + ts;
            }

#pragma unroll
        for (int mt = 0; mt < 2; mt++)
#pragma unroll
            for (int nt = 0; nt < 4; nt++) {
                o[mt][nt][0] *= corr[mt][0];
                o[mt][nt][1] *= corr[mt][0];
                o[mt][nt][2] *= corr[mt][1];
                o[mt][nt][3] *= corr[mt][1];
            }

#pragma unroll
        for (int ks = 0; ks < 8; ks++) {
            const int kc = ks * 8;
            uint32_t af[2][4], bf[4][2];
#pragma unroll
            for (int mt = 0; mt < 2; mt++) {
                int r = warpm * 32 + mt * 16 + g;
                uint2 a0 = *(const uint2*)&Ps[r * PS2 + kc + q * 2];
                uint2 a1 = *(const uint2*)&Ps[(r + 8) * PS2 + kc + q * 2];
                af[mt][0] = a0.x; af[mt][2] = a0.y;
                af[mt][1] = a1.x; af[mt][3] = a1.y;
            }
#pragma unroll
            for (int nt = 0; nt < 4; nt++) {
                int c = warpn * 32 + nt * 8 + g;
                bf[nt][0] = Vs[(kc + q) * VS2 + c];
                bf[nt][1] = Vs[(kc + q + 4) * VS2 + c];
            }
#pragma unroll
            for (int mt = 0; mt < 2; mt++)
#pragma unroll
                for (int nt = 0; nt < 4; nt++)
                    mma_tf32(o[mt][nt], af[mt], bf[nt]);
        }

        __syncthreads();           // D: all warps done with Ps/Vs
        if (n + 1 < NIT) issueV(n + 1);
        CP_COMMIT();
    }

#pragma unroll
    for (int mt = 0; mt < 2; mt++) {
        float inv0 = 1.0f / rlr[mt][0];
        float inv1 = 1.0f / rlr[mt][1];
        int s0 = mblk * 128 + row_base + mt * 16;
#pragma unroll
        for (int nt = 0; nt < 4; nt++) {
            int col = warpn * 32 + nt * 8 + 2 * q;
            float* op0 = O + ((size_t)(b * S_ + s0) * QH_ + qh) * HD_ + col;
            float* op1 = O + ((size_t)(b * S_ + s0 + 8) * QH_ + qh) * HD_ + col;
            *(uint2*)op0 = make_uint2(f2tf32(o[mt][nt][0] * inv0), f2tf32(o[mt][nt][1] * inv0));
            *(uint2*)op1 = make_uint2(f2tf32(o[mt][nt][2] * inv1), f2tf32(o[mt][nt][3] * inv1));
        }
    }
}

// ---------------------------------------------------------------------------
// Launch
// ---------------------------------------------------------------------------
extern "C" void kernel_launch(void* const* d_in, const int* in_sizes, int n_in,
                              void* d_out, int out_size) {
    const float* x         = (const float*)d_in[0];
    const int*   positions = (const int*)d_in[1];
    const float* Wq        = (const float*)d_in[2];
    const float* Wk        = (const float*)d_in[3];
    const float* Wv        = (const float*)d_in[4];
    const float* Wo        = (const float*)d_in[5];
    float* out = (float*)d_out;

    float *q, *k, *v, *att, *xr, *wq, *wk, *wv, *wo;
    cudaGetSymbolAddress((void**)&q,   g_q);
    cudaGetSymbolAddress((void**)&k,   g_k);
    cudaGetSymbolAddress((void**)&v,   g_v);
    cudaGetSymbolAddress((void**)&att, g_att);
    cudaGetSymbolAddress((void**)&xr,  g_xr);
    cudaGetSymbolAddress((void**)&wq,  g_wq);
    cudaGetSymbolAddress((void**)&wk,  g_wk);
    cudaGetSymbolAddress((void**)&wv,  g_wv);
    cudaGetSymbolAddress((void**)&wo,  g_wo);

    cudaFuncSetAttribute(qkv_proj, cudaFuncAttributeMaxDynamicSharedMemorySize, GEMM_SMEM);
    cudaFuncSetAttribute(o_proj,   cudaFuncAttributeMaxDynamicSharedMemorySize, GEMM_SMEM);
    cudaFuncSetAttribute(flash_tc2, cudaFuncAttributeMaxDynamicSharedMemorySize, F2_SMEM);

    // Pre-round operands to tf32 (hoisted cvt.rna; bit-identical dataflow)
    {
        int nx = B_ * S_ * D_ / 4;
        round_tf32_kernel<<<(nx + 255) / 256, 256>>>(xr, x, nx);
        int nq = QH_ * D_ * HD_ / 4;
        round_tf32_kernel<<<(nq + 255) / 256, 256>>>(wq, Wq, nq);
        int nk = KH_ * D_ * HD_ / 4;
        round_tf32_kernel<<<(nk + 255) / 256, 256>>>(wk, Wk, nk);
        round_tf32_kernel<<<(nk + 255) / 256, 256>>>(wv, Wv, nk);
        int no = QH_ * HD_ * D_ / 4;
        round_tf32_kernel<<<(no + 255) / 256, 256>>>(wo, Wo, no);
    }

    // Merged QKV projection (128x256 tiles)
    qkv_proj<<<dim3(12, M_ROWS / 128), 256, GEMM_SMEM>>>(xr, wq, wk, wv, q, k, v);

    // RoPE (emits tf32-rounded q/k)
    {
        int tq = B_ * S_ * QH_ * (HD_ / 2);
        int tk = B_ * S_ * KH_ * (HD_ / 2);
        rope_kernel<<<(tq + 255) / 256, 256>>>(q, positions, QH_, tq);
        rope_kernel<<<(tk + 255) / 256, 256>>>(k, positions, KH_, tk);
    }

    // Flash attention v2b
    flash_tc2<<<dim3(S_ / 128, B_ * QH_), 512, F2_SMEM>>>(q, k, v, att);

    // Output projection (128x256 tiles)
    o_proj<<<dim3(D_ / 256, M_ROWS / 128), 256, GEMM_SMEM>>>(att, wo, out);
}

// round 11
// speedup vs baseline: 4.4004x; 1.0203x over previous
#include <cuda_runtime.h>
#include <math.h>
#include <stdint.h>

// Problem dimensions (fixed by the dataset)
#define B_  2
#define S_  2048
#define D_  2048
#define QH_ 16
#define KH_ 4
#define HD_ 128
#define M_ROWS (B_ * S_)   // 4096

// ---------------------------------------------------------------------------
// Scratch (no allocations allowed -> __device__ globals)
// ---------------------------------------------------------------------------
__device__ float g_q[B_ * S_ * QH_ * HD_];   // 8M floats (pair-permuted cols)
__device__ float g_k[B_ * S_ * KH_ * HD_];   // 2M (pair-permuted cols)
__device__ float g_v[B_ * S_ * KH_ * HD_];   // 2M (natural)
__device__ float g_att[B_ * S_ * QH_ * HD_]; // 8M
__device__ float g_xr[B_ * S_ * D_];         // 8M  (tf32-rounded x)
__device__ float g_wq[QH_ * D_ * HD_];       // 4M  (tf32-rounded weights)
__device__ float g_wk[KH_ * D_ * HD_];       // 1M
__device__ float g_wv[KH_ * D_ * HD_];       // 1M
__device__ float g_wo[QH_ * HD_ * D_];       // 4M
__device__ float2 g_rt[S_ * 64];             // sin/cos table

// ---------------------------------------------------------------------------
// TF32 / cp.async helpers
// ---------------------------------------------------------------------------
__device__ __forceinline__ uint32_t f2tf32(float f) {
    uint32_t u;
    asm("cvt.rna.tf32.f32 %0, %1;" : "=r"(u) : "f"(f));
    return u;
}

__device__ __forceinline__ void mma_tf32(float* c, const uint32_t* a, const uint32_t* b) {
    asm volatile(
        "mma.sync.aligned.m16n8k8.row.col.f32.tf32.tf32.f32 "
        "{%0,%1,%2,%3}, {%4,%5,%6,%7}, {%8,%9}, {%0,%1,%2,%3};\n"
        : "+f"(c[0]), "+f"(c[1]), "+f"(c[2]), "+f"(c[3])
        : "r"(a[0]), "r"(a[1]), "r"(a[2]), "r"(a[3]), "r"(b[0]), "r"(b[1]));
}

__device__ __forceinline__ void cp_async16(void* sptr, const void* gptr) {
    uint32_t sa = (uint32_t)__cvta_generic_to_shared(sptr);
    asm volatile("cp.async.cg.shared.global [%0], [%1], 16;\n" :: "r"(sa), "l"(gptr));
}
#define CP_COMMIT() asm volatile("cp.async.commit_group;\n" ::: "memory")
#define CP_WAIT1()  asm volatile("cp.async.wait_group 1;\n" ::: "memory")

// pair permutation within an 8-group: j -> 2*(j&3) | (j>>2)
__device__ __forceinline__ int perm8(int j) { return (((j) & 3) << 1) | (((j) >> 2) & 1); }

// ---------------------------------------------------------------------------
// Elementwise tf32 rounding pass (vectorized)
// ---------------------------------------------------------------------------
__global__ void round_tf32_kernel(float* __restrict__ dst, const float* __restrict__ src,
                                  int n4) {
    int i = blockIdx.x * blockDim.x + threadIdx.x;
    if (i >= n4) return;
    float4 v = ((const float4*)src)[i];
    uint4 t = make_uint4(f2tf32(v.x), f2tf32(v.y), f2tf32(v.z), f2tf32(v.w));
    ((uint4*)dst)[i] = t;
}

// ---------------------------------------------------------------------------
// Pipelined TF32 GEMM body. CTA tile 128x256, BK=32, 3-stage cp.async.
// 256 threads = 8 warps (2m x 4n), warp tile 64x64, m16n8k8.
// PERMC: epilogue stores columns pair-permuted within 8-groups (Q/K outputs).
// ROUNDC: epilogue rounds C to tf32 (V output).
// ---------------------------------------------------------------------------
#define GSTAGES 3
#define ASTG (128 * 36)
#define BSTG (32 * 264)
#define STG_WORDS (ASTG + BSTG)
#define GEMM_SMEM (GSTAGES * STG_WORDS * 4)

template <bool HEADB, bool PERMC, bool ROUNDC>
__device__ __forceinline__ void gemm_body(const float* __restrict__ A,
                                          const float* __restrict__ W,
                                          float* __restrict__ C,
                                          int K, int ldc, int wld,
                                          int brow, int ccol, float* smem) {
    const int tid  = threadIdx.x;
    const int lane = tid & 31;
    const int wid  = tid >> 5;
    const int warpm = wid >> 2;
    const int warpn = wid & 3;
    const int g = lane >> 2;
    const int q = lane & 3;

    const int am  = tid >> 3;
    const int ak4 = (tid & 7) << 2;
    const int NITER = K >> 5;

    const float* Abase = A + (size_t)(brow + am) * K + ak4;

    float acc[4][8][4];
#pragma unroll
    for (int mt = 0; mt < 4; mt++)
#pragma unroll
        for (int nt = 0; nt < 8; nt++)
#pragma unroll
            for (int i = 0; i < 4; i++) acc[mt][nt][i] = 0.f;

    auto issue_tile = [&](int t) {
        float* As = smem + (t % GSTAGES) * STG_WORDS;
        float* Bs = As + ASTG;
        const int k0 = t << 5;
        const float* ap = Abase + k0;
#pragma unroll
        for (int p = 0; p < 4; p++)
            cp_async16(As + (am + 32 * p) * 36 + ak4, ap + (size_t)(32 * p) * K);
#pragma unroll
        for (int p = 0; p < 8; p++) {
            int idx = tid + p * 256;
            int row = idx >> 6;
            int c4  = (idx & 63) << 2;
            const float* wp;
            if (HEADB) {
                wp = W + (size_t)(c4 >> 7) * K * 128 + (size_t)(k0 + row) * 128 + (c4 & 127);
            } else {
                wp = W + (size_t)(k0 + row) * wld + c4;
            }
            cp_async16(Bs + row * 264 + c4, wp);
        }
    };

    issue_tile(0); CP_COMMIT();
    issue_tile(1); CP_COMMIT();

    for (int i = 0; i < NITER; i++) {
        CP_WAIT1();
        __syncthreads();
        if (i + 2 < NITER) issue_tile(i + 2);
        CP_COMMIT();

        const uint32_t* As = (const uint32_t*)(smem + (i % GSTAGES) * STG_WORDS);
        const uint32_t* Bs = As + ASTG;

#pragma unroll
        for (int kk = 0; kk < 4; kk++) {
            const int kc = kk * 8;
            uint32_t af[4][4];
            uint32_t bf[8][2];
#pragma unroll
            for (int mt = 0; mt < 4; mt++) {
                int r = warpm * 64 + mt * 16 + g;
                af[mt][0] = As[r * 36 + kc + q];
                af[mt][1] = As[(r + 8) * 36 + kc + q];
                af[mt][2] = As[r * 36 + kc + q + 4];
                af[mt][3] = As[(r + 8) * 36 + kc + q + 4];
            }
#pragma unroll
            for (int nt = 0; nt < 8; nt++) {
                int c = warpn * 64 + nt * 8 + g;
                bf[nt][0] = Bs[(kc + q) * 264 + c];
                bf[nt][1] = Bs[(kc + q + 4) * 264 + c];
            }
#pragma unroll
            for (int mt = 0; mt < 4; mt++)
#pragma unroll
                for (int nt = 0; nt < 8; nt++)
                    mma_tf32(acc[mt][nt], af[mt], bf[nt]);
        }
    }

    // ---- epilogue ----
    const int p0 = perm8(2 * q);
    const int p1 = perm8(2 * q + 1);
#pragma unroll
    for (int mt = 0; mt < 4; mt++) {
        int r = brow + warpm * 64 + mt * 16 + g;
#pragma unroll
        for (int nt = 0; nt < 8; nt++) {
            if (PERMC) {
                int cb = ccol + warpn * 64 + nt * 8;
                C[(size_t)r * ldc + cb + p0] = acc[mt][nt][0];
                C[(size_t)r * ldc + cb + p1] = acc[mt][nt][1];
                C[(size_t)(r + 8) * ldc + cb + p0] = acc[mt][nt][2];
                C[(size_t)(r + 8) * ldc + cb + p1] = acc[mt][nt][3];
            } else {
                int c = ccol + warpn * 64 + nt * 8 + 2 * q;
                if (ROUNDC) {
                    uint2 c0 = make_uint2(f2tf32(acc[mt][nt][0]), f2tf32(acc[mt][nt][1]));
                    uint2 c1 = make_uint2(f2tf32(acc[mt][nt][2]), f2tf32(acc[mt][nt][3]));
                    *(uint2*)&C[(size_t)r * ldc + c] = c0;
                    *(uint2*)&C[(size_t)(r + 8) * ldc + c] = c1;
                } else {
                    *(float2*)&C[(size_t)r * ldc + c] = make_float2(acc[mt][nt][0], acc[mt][nt][1]);
                    *(float2*)&C[(size_t)(r + 8) * ldc + c] = make_float2(acc[mt][nt][2], acc[mt][nt][3]);
                }
            }
        }
    }
}

// Merged QKV projection: grid (12 head-pair blocks, 32 row-blocks)
__global__ __launch_bounds__(256) void qkv_proj(const float* __restrict__ x,
                                                const float* __restrict__ Wq,
                                                const float* __restrict__ Wk,
                                                const float* __restrict__ Wv,
                                                float* __restrict__ qo,
                                                float* __restrict__ ko,
                                                float* __restrict__ vo) {
    extern __shared__ float sm_f[];
    const int hp = blockIdx.x;
    const int brow = blockIdx.y * 128;
    if (hp < 8) {
        gemm_body<true, true, false>(x, Wq + (size_t)(2 * hp) * D_ * HD_, qo,
                                     D_, QH_ * HD_, HD_, brow, hp * 256, sm_f);
    } else if (hp < 10) {
        int p = hp - 8;
        gemm_body<true, true, false>(x, Wk + (size_t)(2 * p) * D_ * HD_, ko,
                                     D_, KH_ * HD_, HD_, brow, p * 256, sm_f);
    } else {
        int p = hp - 10;
        gemm_body<true, false, true>(x, Wv + (size_t)(2 * p) * D_ * HD_, vo,
                                     D_, KH_ * HD_, HD_, brow, p * 256, sm_f);
    }
}

// Output projection: grid (8 col-blocks of 256, 32 row-blocks)
__global__ __launch_bounds__(256) void o_proj(const float* __restrict__ att,
                                              const float* __restrict__ Wo,
                                              float* __restrict__ out) {
    extern __shared__ float sm_f[];
    const int bcol = blockIdx.x * 256;
    const int brow = blockIdx.y * 128;
    gemm_body<false, false, false>(att, Wo + bcol, out, QH_ * HD_, D_, D_, brow, bcol, sm_f);
}

// ---------------------------------------------------------------------------
// sin/cos table: rt[s][hp] = (cos(ang), sin(ang)) — bit-identical ops to before
// ---------------------------------------------------------------------------
__global__ void sincos_kernel(float2* __restrict__ rt, const int* __restrict__ positions) {
    int i = blockIdx.x * blockDim.x + threadIdx.x;
    if (i >= S_ * 64) return;
    int hp = i & 63;
    int s  = i >> 6;
    float pos = (float)positions[s];
    float ts  = expf(((float)hp / 64.f) * 9.21034037197618f /* ln(1e4) */);
    float ang = pos / ts;
    rt[i] = make_float2(cosf(ang), sinf(ang));
}

// ---------------------------------------------------------------------------
// RoPE (in-place) on pair-permuted [B, S, NH, 128]; folds `scale` into the
// rotation (Q gets 1/sqrt(d), K gets 1). Each thread owns its 2 physical slots.
// ---------------------------------------------------------------------------
__global__ void rope_kernel(float* __restrict__ x, const float2* __restrict__ rt,
                            int NH, int total, float scale) {
    int i = blockIdx.x * blockDim.x + threadIdx.x;
    if (i >= total) return;
    int hp = i & 63;            // logical half-dim index
    int rest = i >> 6;
    int nh = rest % NH;
    int s  = (rest / NH) % S_;
    int b  = rest / (NH * S_);

    float2 cs2 = rt[s * 64 + hp];
    float cs = cs2.x * scale;
    float sn = cs2.y * scale;

    int p = (hp & ~7) | perm8(hp & 7);   // physical (pair-permuted) position
    size_t base = ((size_t)(b * S_ + s) * NH + nh) * HD_;
    float x1 = x[base + p];
    float x2 = x[base + p + 64];
    x[base + p]      = __uint_as_float(f2tf32(x1 * cs - x2 * sn));
    x[base + p + 64] = __uint_as_float(f2tf32(x2 * cs + x1 * sn));
}

// ---------------------------------------------------------------------------
// Flash attention v3: TF32 tensor cores, causal, GQA.
// 128-query tiles, 512 threads = 16 warps (4m x 4n).
// Q and K gmem are pair-permuted -> cp.async straight copies; both A and B
// fragments of QK load as LDS.64. Scale pre-folded into Q.
// ---------------------------------------------------------------------------
#define QS2 136
#define KS2 136
#define VS2 136
#define PS2 72
#define KTILE_W (64 * KS2)

#define F2_SMEM ((128 * QS2 + 2 * KTILE_W + 64 * VS2 + 128 * PS2 + 512 + 512) * 4)

__global__ __launch_bounds__(512) void flash_tc2(const float* __restrict__ Q,
                                                 const float* __restrict__ K,
                                                 const float* __restrict__ V,
                                                 float* __restrict__ O) {
    extern __shared__ uint32_t sm_u[];
    uint32_t* Qs = sm_u;                    // [128][136] pair layout
    uint32_t* Kb = Qs + 128 * QS2;          // 2 x [64][136] pair layout
    uint32_t* Vs = Kb + 2 * KTILE_W;        // [64][136] natural
    uint32_t* Ps = Vs + 64 * VS2;           // [128][72] pair layout
    float* smax  = (float*)(Ps + 128 * PS2);   // [4][128]
    float* ssum  = smax + 512;                 // [4][128]

    const int tid  = threadIdx.x;
    const int lane = tid & 31;
    const int wid  = tid >> 5;
    const int warpm = wid >> 2;
    const int warpn = wid & 3;
    const int g = lane >> 2;
    const int q = lane & 3;

    const int mblk = gridDim.x - 1 - blockIdx.x;
    const int bq = blockIdx.y;
    const int b  = bq / QH_;
    const int qh = bq % QH_;
    const int kvh = qh / (QH_ / KH_);

    float rmr[2][2], rlr[2][2];
#pragma unroll
    for (int mt = 0; mt < 2; mt++)
#pragma unroll
        for (int h = 0; h < 2; h++) { rmr[mt][h] = -INFINITY; rlr[mt][h] = 0.f; }

    float o[2][4][4];
#pragma unroll
    for (int mt = 0; mt < 2; mt++)
#pragma unroll
        for (int nt = 0; nt < 4; nt++)
#pragma unroll
            for (int i = 0; i < 4; i++) o[mt][nt][i] = 0.f;

    const int row_base = warpm * 32 + g;
    const int qkcol_base = warpn * 16 + 2 * q;
    const int NIT = 2 * mblk + 2;

    auto issueQ = [&]() {
        for (int idx = tid; idx < 128 * 32; idx += 512) {
            int r  = idx >> 5;
            int c4 = (idx & 31) << 2;
            cp_async16(Qs + r * QS2 + c4,
                       Q + ((size_t)(b * S_ + mblk * 128 + r) * QH_ + qh) * HD_ + c4);
        }
    };
    auto issueK = [&](int n) {
        uint32_t* kd = Kb + (n & 1) * KTILE_W;
        for (int idx = tid; idx < 64 * 32; idx += 512) {
            int r  = idx >> 5;
            int c4 = (idx & 31) << 2;
            cp_async16(kd + r * KS2 + c4,
                       K + ((size_t)(b * S_ + n * 64 + r) * KH_ + kvh) * HD_ + c4);
        }
    };
    auto issueV = [&](int n) {
        for (int idx = tid; idx < 64 * 32; idx += 512) {
            int r  = idx >> 5;
            int c4 = (idx & 31) << 2;
            cp_async16(Vs + r * VS2 + c4,
                       V + ((size_t)(b * S_ + n * 64 + r) * KH_ + kvh) * HD_ + c4);
        }
    };

    issueQ(); issueK(0); issueV(0); CP_COMMIT();

    for (int n = 0; n < NIT; n++) {
        if (n + 1 < NIT) issueK(n + 1);
        CP_COMMIT();
        CP_WAIT1();
        __syncthreads();           // A: Q(first), K(n), V(n) ready

        const uint32_t* Kst = Kb + (n & 1) * KTILE_W;

        // ---- QK^T (scores pre-scaled via Q) ----
        float s[2][2][4];
#pragma unroll
        for (int mt = 0; mt < 2; mt++)
#pragma unroll
            for (int nt = 0; nt < 2; nt++)
#pragma unroll
                for (int i = 0; i < 4; i++) s[mt][nt][i] = 0.f;

#pragma unroll
        for (int ks = 0; ks < 16; ks++) {
            const int kc = ks * 8;
            uint32_t af[2][4], bf[2][2];
#pragma unroll
            for (int mt = 0; mt < 2; mt++) {
                int r = warpm * 32 + mt * 16 + g;
                uint2 a0 = *(const uint2*)&Qs[r * QS2 + kc + q * 2];
                uint2 a1 = *(const uint2*)&Qs[(r + 8) * QS2 + kc + q * 2];
                af[mt][0] = a0.x; af[mt][2] = a0.y;
                af[mt][1] = a1.x; af[mt][3] = a1.y;
            }
#pragma unroll
            for (int nt = 0; nt < 2; nt++) {
                int c = warpn * 16 + nt * 8 + g;
                uint2 b2 = *(const uint2*)&Kst[c * KS2 + kc + q * 2];
                bf[nt][0] = b2.x;
                bf[nt][1] = b2.y;
            }
#pragma unroll
            for (int mt = 0; mt < 2; mt++)
#pragma unroll
                for (int nt = 0; nt < 2; nt++)
                    mma_tf32(s[mt][nt], af[mt], bf[nt]);
        }

        // ---- causal mask (only on the diagonal pair of tiles) ----
        if (n >= 2 * mblk) {
            const int gr_base = mblk * 128 + row_base;
            const int gc_base = n * 64 + qkcol_base;
#pragma unroll
            for (int mt = 0; mt < 2; mt++) {
                int gr0 = gr_base + mt * 16;
                int gr1 = gr0 + 8;
#pragma unroll
                for (int nt = 0; nt < 2; nt++) {
                    int gc0 = gc_base + nt * 8;
                    int gc1 = gc0 + 1;
                    if (gc0 > gr0) s[mt][nt][0] = -1e9f;
                    if (gc1 > gr0) s[mt][nt][1] = -1e9f;
                    if (gc0 > gr1) s[mt][nt][2] = -1e9f;
                    if (gc1 > gr1) s[mt][nt][3] = -1e9f;
                }
            }
        }

        // ---- partial row max -> smax ----
#pragma unroll
        for (int mt = 0; mt < 2; mt++)
#pragma unroll
            for (int h = 0; h < 2; h++) {
                float pm = fmaxf(fmaxf(s[mt][0][2 * h], s[mt][0][2 * h + 1]),
                                 fmaxf(s[mt][1][2 * h], s[mt][1][2 * h + 1]));
                pm = fmaxf(pm, __shfl_xor_sync(0xFFFFFFFF, pm, 1));
                pm = fmaxf(pm, __shfl_xor_sync(0xFFFFFFFF, pm, 2));
                if (q == 0) smax[warpn * 128 + row_base + mt * 16 + 8 * h] = pm;
            }
        __syncthreads();           // B: smax complete

        // ---- m update (registers), exp, P store, partial sums ----
        const int poff0 = perm8(2 * q);
        const int poff1 = perm8(2 * q + 1);
        float corr[2][2];
#pragma unroll
        for (int mt = 0; mt < 2; mt++)
#pragma unroll
            for (int h = 0; h < 2; h++) {
                int row = row_base + mt * 16 + 8 * h;
                float m_tile = fmaxf(fmaxf(smax[row], smax[128 + row]),
                                     fmaxf(smax[256 + row], smax[384 + row]));
                float m_old = rmr[mt][h];
                float m_new = fmaxf(m_old, m_tile);
                corr[mt][h] = __expf(m_old - m_new);
                rmr[mt][h] = m_new;

                float psum = 0.f;
#pragma unroll
                for (int nt = 0; nt < 2; nt++) {
                    float p0 = __expf(s[mt][nt][2 * h] - m_new);
                    float p1 = __expf(s[mt][nt][2 * h + 1] - m_new);
                    psum += p0 + p1;
                    uint32_t* pb = Ps + row * PS2 + (warpn * 2 + nt) * 8;
                    pb[poff0] = f2tf32(p0);
                    pb[poff1] = f2tf32(p1);
                }
                psum += __shfl_xor_sync(0xFFFFFFFF, psum, 1);
                psum += __shfl_xor_sync(0xFFFFFFFF, psum, 2);
                if (q == 0) ssum[warpn * 128 + row] = psum;
            }
        __syncthreads();           // C: Ps + ssum complete

        // ---- l update (registers) ----
#pragma unroll
        for (int mt = 0; mt < 2; mt++)
#pragma unroll
            for (int h = 0; h < 2; h++) {
                int row = row_base + mt * 16 + 8 * h;
                float ts = ssum[row] + ssum[128 + row] + ssum[256 + row] + ssum[384 + row];
                rlr[mt][h] = rlr[mt][h] * corr[mt][h] + ts;
            }

        // ---- rescale O, then PV mma ----
#pragma unroll
        for (int mt = 0; mt < 2; mt++)
#pragma unroll
            for (int nt = 0; nt < 4; nt++) {
                o[mt][nt][0] *= corr[mt][0];
                o[mt][nt][1] *= corr[mt][0];
                o[mt][nt][2] *= corr[mt][1];
                o[mt][nt][3] *= corr[mt][1];
            }

#pragma unroll
        for (int ks = 0; ks < 8; ks++) {
            const int kc = ks * 8;
            uint32_t af[2][4], bf[4][2];
#pragma unroll
            for (int mt = 0; mt < 2; mt++) {
                int r = warpm * 32 + mt * 16 + g;
                uint2 a0 = *(const uint2*)&Ps[r * PS2 + kc + q * 2];
                uint2 a1 = *(const uint2*)&Ps[(r + 8) * PS2 + kc + q * 2];
                af[mt][0] = a0.x; af[mt][2] = a0.y;
                af[mt][1] = a1.x; af[mt][3] = a1.y;
            }
#pragma unroll
            for (int nt = 0; nt < 4; nt++) {
                int c = warpn * 32 + nt * 8 + g;
                bf[nt][0] = Vs[(kc + q) * VS2 + c];
                bf[nt][1] = Vs[(kc + q + 4) * VS2 + c];
            }
#pragma unroll
            for (int mt = 0; mt < 2; mt++)
#pragma unroll
                for (int nt = 0; nt < 4; nt++)
                    mma_tf32(o[mt][nt], af[mt], bf[nt]);
        }

        __syncthreads();           // D: all warps done with Ps/Vs
        if (n + 1 < NIT) issueV(n + 1);
        CP_COMMIT();
    }

    // ---- epilogue: normalize + round to tf32 (o_proj consumes raw) ----
#pragma unroll
    for (int mt = 0; mt < 2; mt++) {
        float inv0 = 1.0f / rlr[mt][0];
        float inv1 = 1.0f / rlr[mt][1];
        int s0 = mblk * 128 + row_base + mt * 16;
#pragma unroll
        for (int nt = 0; nt < 4; nt++) {
            int col = warpn * 32 + nt * 8 + 2 * q;
            float* op0 = O + ((size_t)(b * S_ + s0) * QH_ + qh) * HD_ + col;
            float* op1 = O + ((size_t)(b * S_ + s0 + 8) * QH_ + qh) * HD_ + col;
            *(uint2*)op0 = make_uint2(f2tf32(o[mt][nt][0] * inv0), f2tf32(o[mt][nt][1] * inv0));
            *(uint2*)op1 = make_uint2(f2tf32(o[mt][nt][2] * inv1), f2tf32(o[mt][nt][3] * inv1));
        }
    }
}

// ---------------------------------------------------------------------------
// Launch
// ---------------------------------------------------------------------------
extern "C" void kernel_launch(void* const* d_in, const int* in_sizes, int n_in,
                              void* d_out, int out_size) {
    const float* x         = (const float*)d_in[0];
    const int*   positions = (const int*)d_in[1];
    const float* Wq        = (const float*)d_in[2];
    const float* Wk        = (const float*)d_in[3];
    const float* Wv        = (const float*)d_in[4];
    const float* Wo        = (const float*)d_in[5];
    float* out = (float*)d_out;

    float *q, *k, *v, *att, *xr, *wq, *wk, *wv, *wo;
    float2* rt;
    cudaGetSymbolAddress((void**)&q,   g_q);
    cudaGetSymbolAddress((void**)&k,   g_k);
    cudaGetSymbolAddress((void**)&v,   g_v);
    cudaGetSymbolAddress((void**)&att, g_att);
    cudaGetSymbolAddress((void**)&xr,  g_xr);
    cudaGetSymbolAddress((void**)&wq,  g_wq);
    cudaGetSymbolAddress((void**)&wk,  g_wk);
    cudaGetSymbolAddress((void**)&wv,  g_wv);
    cudaGetSymbolAddress((void**)&wo,  g_wo);
    cudaGetSymbolAddress((void**)&rt,  g_rt);

    cudaFuncSetAttribute(qkv_proj, cudaFuncAttributeMaxDynamicSharedMemorySize, GEMM_SMEM);
    cudaFuncSetAttribute(o_proj,   cudaFuncAttributeMaxDynamicSharedMemorySize, GEMM_SMEM);
    cudaFuncSetAttribute(flash_tc2, cudaFuncAttributeMaxDynamicSharedMemorySize, F2_SMEM);

    // Pre-round operands to tf32; build the sin/cos table
    {
        int nx = B_ * S_ * D_ / 4;
        round_tf32_kernel<<<(nx + 255) / 256, 256>>>(xr, x, nx);
        int nq = QH_ * D_ * HD_ / 4;
        round_tf32_kernel<<<(nq + 255) / 256, 256>>>(wq, Wq, nq);
        int nk = KH_ * D_ * HD_ / 4;
        round_tf32_kernel<<<(nk + 255) / 256, 256>>>(wk, Wk, nk);
        round_tf32_kernel<<<(nk + 255) / 256, 256>>>(wv, Wv, nk);
        int no = QH_ * HD_ * D_ / 4;
        round_tf32_kernel<<<(no + 255) / 256, 256>>>(wo, Wo, no);
        sincos_kernel<<<(S_ * 64 + 255) / 256, 256>>>(rt, positions);
    }

    // Merged QKV projection (Q/K written pair-permuted; V rounded)
    qkv_proj<<<dim3(12, M_ROWS / 128), 256, GEMM_SMEM>>>(xr, wq, wk, wv, q, k, v);

    // RoPE in-place on permuted layout; Q absorbs the softmax scale
    {
        int tq = B_ * S_ * QH_ * (HD_ / 2);
        int tk = B_ * S_ * KH_ * (HD_ / 2);
        rope_kernel<<<(tq + 255) / 256, 256>>>(q, rt, QH_, tq, 0.08838834764831845f);
        rope_kernel<<<(tk + 255) / 256, 256>>>(k, rt, KH_, tk, 1.0f);
    }

    // Flash attention v3
    flash_tc2<<<dim3(S_ / 128, B_ * QH_), 512, F2_SMEM>>>(q, k, v, att);

    // Output projection
    o_proj<<<dim3(D_ / 256, M_ROWS / 128), 256, GEMM_SMEM>>>(att, wo, out);
}